// round 8
// baseline (speedup 1.0000x reference)
#include <cuda_runtime.h>
#include <cuda_fp16.h>
#include <cstdint>

#define BB 4
#define SS 2048
#define EE 1024
#define MM (BB*SS)

// ---------------- PTX helpers (baseline ISA only; no sm_103a-accel features) ----------------
__device__ __forceinline__ uint32_t smem_u32(const void* p) {
    uint32_t a;
    asm("{ .reg .u64 t; cvta.to.shared.u64 t, %1; cvt.u32.u64 %0, t; }" : "=r"(a) : "l"(p));
    return a;
}

#define LDSM4(r0, r1, r2, r3, addr) \
    asm volatile("ldmatrix.sync.aligned.m8n8.x4.shared.b16 {%0,%1,%2,%3}, [%4];" \
        : "=r"(r0), "=r"(r1), "=r"(r2), "=r"(r3) : "r"(addr))

#define MMA16816(d, a, b0, b1) \
    asm volatile("mma.sync.aligned.m16n8k16.row.col.f32.f16.f16.f32 " \
        "{%0,%1,%2,%3}, {%4,%5,%6,%7}, {%8,%9}, {%0,%1,%2,%3};" \
        : "+f"((d)[0]), "+f"((d)[1]), "+f"((d)[2]), "+f"((d)[3]) \
        : "r"((a)[0]), "r"((a)[1]), "r"((a)[2]), "r"((a)[3]), "r"(b0), "r"(b1))

#define CP_ASYNC16(saddr, gptr) \
    asm volatile("cp.async.cg.shared.global [%0], [%1], 16;" :: "r"(saddr), "l"(gptr) : "memory")
#define CP_COMMIT() asm volatile("cp.async.commit_group;" ::: "memory")
#define CP_WAIT2()  asm volatile("cp.async.wait_group 2;" ::: "memory")

// ---------------- scratch (device globals, allocation-free) ----------------
__device__ __align__(1024) __half g_qin_hi[(size_t)MM * EE], g_qin_lo[(size_t)MM * EE];
__device__ __align__(1024) __half g_kin_hi[(size_t)MM * EE], g_kin_lo[(size_t)MM * EE];
__device__ __align__(1024) __half g_vin_hi[(size_t)MM * EE], g_vin_lo[(size_t)MM * EE];
__device__ __align__(1024) __half g_wq_hi[(size_t)EE * EE];
__device__ __align__(1024) __half g_wk_hi[(size_t)EE * EE];
__device__ __align__(1024) __half g_wv_hi[(size_t)EE * EE];
__device__ __align__(1024) __half g_q_hi[(size_t)MM * EE], g_q_lo[(size_t)MM * EE];
__device__ __align__(1024) __half g_k_hi[(size_t)MM * EE];
__device__ __align__(1024) float  g_vproj[(size_t)MM * EE];
__device__ __align__(1024) __half g_vt_hi[(size_t)MM * EE];
__device__ __align__(1024) float  g_sc[(size_t)BB * SS * SS];
__device__ __align__(1024) __half g_at_hi[(size_t)BB * SS * SS], g_at_lo[(size_t)BB * SS * SS];

// ---------------- split / convert / transpose / softmax ----------------
__global__ void __launch_bounds__(256)
split_kernel(const float4* __restrict__ x, ushort4* __restrict__ hi, ushort4* __restrict__ lo, int n4)
{
    int i = blockIdx.x * blockDim.x + threadIdx.x;
    if (i >= n4) return;
    float4 v = x[i];
    __half hx = __float2half_rn(v.x), hy = __float2half_rn(v.y);
    __half hz = __float2half_rn(v.z), hw = __float2half_rn(v.w);
    ushort4 h, l;
    h.x = __half_as_ushort(hx); h.y = __half_as_ushort(hy);
    h.z = __half_as_ushort(hz); h.w = __half_as_ushort(hw);
    l.x = __half_as_ushort(__float2half_rn(v.x - __half2float(hx)));
    l.y = __half_as_ushort(__float2half_rn(v.y - __half2float(hy)));
    l.z = __half_as_ushort(__float2half_rn(v.z - __half2float(hz)));
    l.w = __half_as_ushort(__float2half_rn(v.w - __half2float(hw)));
    hi[i] = h; lo[i] = l;
}

__global__ void __launch_bounds__(256)
conv_kernel(const float4* __restrict__ x, ushort4* __restrict__ hi, int n4)
{
    int i = blockIdx.x * blockDim.x + threadIdx.x;
    if (i >= n4) return;
    float4 v = x[i];
    ushort4 h;
    h.x = __half_as_ushort(__float2half_rn(v.x));
    h.y = __half_as_ushort(__float2half_rn(v.y));
    h.z = __half_as_ushort(__float2half_rn(v.z));
    h.w = __half_as_ushort(__float2half_rn(v.w));
    hi[i] = h;
}

// transpose: v [BB][SS][EE] fp32 -> vt hi [BB][EE][SS] fp16
__global__ void __launch_bounds__(256)
tsplit_kernel(const float* __restrict__ v, __half* __restrict__ thi)
{
    __shared__ float tile[32][33];
    int b = blockIdx.z;
    int e0 = blockIdx.x * 32, s0 = blockIdx.y * 32;
    int tx = threadIdx.x, ty = threadIdx.y;  // 32 x 8
    #pragma unroll
    for (int k = 0; k < 32; k += 8)
        tile[ty + k][tx] = v[((long long)b * SS + s0 + ty + k) * EE + e0 + tx];
    __syncthreads();
    #pragma unroll
    for (int k = 0; k < 32; k += 8) {
        float val = tile[tx][ty + k];
        long long o = ((long long)b * EE + e0 + ty + k) * SS + s0 + tx;
        thi[o] = __float2half_rn(val);
    }
}

__global__ void __launch_bounds__(256)
softmax_split_kernel(const float* __restrict__ sc, __half* __restrict__ ahi, __half* __restrict__ alo)
{
    const float* p = sc + (long long)blockIdx.x * SS;
    long long obase = (long long)blockIdx.x * SS;
    const int t = threadIdx.x;
    __shared__ float red[8];

    float vals[SS / 256];
    float m = -1e30f;
    #pragma unroll
    for (int i = 0; i < SS / 256; i++) { vals[i] = p[t + i * 256]; m = fmaxf(m, vals[i]); }
    #pragma unroll
    for (int o = 16; o > 0; o >>= 1) m = fmaxf(m, __shfl_xor_sync(0xFFFFFFFFu, m, o));
    if ((t & 31) == 0) red[t >> 5] = m;
    __syncthreads();
    float mm = red[0];
    #pragma unroll
    for (int i = 1; i < 8; i++) mm = fmaxf(mm, red[i]);
    __syncthreads();

    float s = 0.0f;
    #pragma unroll
    for (int i = 0; i < SS / 256; i++) { vals[i] = __expf(vals[i] - mm); s += vals[i]; }
    #pragma unroll
    for (int o = 16; o > 0; o >>= 1) s += __shfl_xor_sync(0xFFFFFFFFu, s, o);
    if ((t & 31) == 0) red[t >> 5] = s;
    __syncthreads();
    float ssum = 0.0f;
    #pragma unroll
    for (int i = 0; i < 8; i++) ssum += red[i];
    float inv = 1.0f / ssum;

    #pragma unroll
    for (int i = 0; i < SS / 256; i++) {
        float r = vals[i] * inv;
        __half h = __float2half_rn(r);
        ahi[obase + t + i * 256] = h;
        alo[obase + t + i * 256] = __float2half_rn(r - __half2float(h));
    }
}

// ---------------- 2-pass split-fp16 tensor-core GEMM ----------------
// C[M,N] = alpha * (Ah+Al)[M,K] * Bh[N,K]^T   (both K-major)
// CTA tile 128x256, K-chunk 32, 8 warps (warp tile 32x128), 4-buffer cp.async.
// Inner loop: preload all B frags, then ah-sweep (32 MMAs, all-distinct acc) then
// al-sweep -- dependent MMAs on any acc slot are 32 issues apart (RAW-stall-free).
static constexpr int TILE_A  = 128 * 80;               // 10240 B (A tile: 128 rows)
static constexpr int TILE_Bb = 256 * 80;               // 20480 B (B tile: 256 rows)
static constexpr int STAGE_B = 2 * TILE_A + TILE_Bb;   // 40960 B: Ah, Al, Bh
static constexpr int NSTAGE  = 4;
static constexpr int GEMM_SMEM = NSTAGE * STAGE_B;     // 163840

template <int OUT_MODE>   // 0: fp32 C ; 1: split fp16 (Chi+Clo) ; 2: fp16 hi only
__global__ void __launch_bounds__(256, 1)
tc_gemm(const __half* __restrict__ Ahi, const __half* __restrict__ Alo,
        const __half* __restrict__ Bhi,
        float* __restrict__ Cf, __half* __restrict__ Chi, __half* __restrict__ Clo,
        int M, int N, int K, long long sA, long long sB, long long sC, float alpha)
{
    extern __shared__ char smem[];
    const uint32_t sbase = smem_u32(smem);
    const int tid = threadIdx.x;
    const int wid = tid >> 5;
    const int lid = tid & 31;
    const int wm = wid & 3;        // warp m block (32 rows)
    const int wn = wid >> 2;       // warp n block (128 cols)

    const int row0 = blockIdx.y * 128;
    const int col0 = blockIdx.x * 256;
    const long long zb = blockIdx.z;
    const __half* A0 = Ahi + zb * sA;
    const __half* A1 = Alo + zb * sA;
    const __half* B0 = Bhi + zb * sB;

    const int NK = K >> 5;  // K-chunks of 32

    auto load_stage = [&](int kc, int st) {
        const uint32_t stb = sbase + (uint32_t)st * STAGE_B;
        #pragma unroll
        for (int j = 0; j < 8; j++) {
            int i = tid + j * 256;      // 0..2047
            const __half* g;
            uint32_t s;
            if (i < 1024) {             // Ah (0..511), Al (512..1023)
                int tile = i >> 9;
                int idx = i & 511;
                int row = idx >> 2, ch = idx & 3;
                const __half* src = (tile == 0) ? A0 : A1;
                g = src + (long long)(row0 + row) * K + kc * 32 + ch * 8;
                s = stb + (uint32_t)(tile * TILE_A + row * 80 + ch * 16);
            } else {                    // Bh: 256 rows
                int idx = i - 1024;
                int row = idx >> 2, ch = idx & 3;
                g = B0 + (long long)(col0 + row) * K + kc * 32 + ch * 8;
                s = stb + (uint32_t)(2 * TILE_A + row * 80 + ch * 16);
            }
            CP_ASYNC16(s, __cvta_generic_to_global((const void*)g));
        }
        CP_COMMIT();
    };

    load_stage(0, 0);
    load_stage(1, 1);
    load_stage(2, 2);

    float acc[2][16][4];
    #pragma unroll
    for (int a = 0; a < 2; a++)
        #pragma unroll
        for (int b = 0; b < 16; b++)
            #pragma unroll
            for (int c = 0; c < 4; c++) acc[a][b][c] = 0.0f;

    const int lrow = lid & 15;
    const int lch  = lid >> 4;

    for (int kc = 0; kc < NK; kc++) {
        CP_WAIT2();
        __syncthreads();

        const int st = kc & 3;
        const uint32_t stb = sbase + (uint32_t)st * STAGE_B;
        #pragma unroll
        for (int ks = 0; ks < 2; ks++) {
            const uint32_t choff = (uint32_t)((ks * 2 + lch) * 16);
            // Preload all fragments for this k16 slice
            uint32_t ah[2][4], al[2][4];
            #pragma unroll
            for (int mf = 0; mf < 2; mf++) {
                uint32_t ra = stb + (uint32_t)((wm * 32 + mf * 16 + lrow) * 80) + choff;
                LDSM4(ah[mf][0], ah[mf][1], ah[mf][2], ah[mf][3], ra);
                LDSM4(al[mf][0], al[mf][1], al[mf][2], al[mf][3], ra + TILE_A);
            }
            uint32_t bh[8][4];
            #pragma unroll
            for (int nb = 0; nb < 8; nb++) {
                uint32_t rb = stb + (uint32_t)(2 * TILE_A + (wn * 128 + nb * 16 + lrow) * 80) + choff;
                LDSM4(bh[nb][0], bh[nb][1], bh[nb][2], bh[nb][3], rb);
            }
            // Pass 1: ah sweep -- 32 MMAs, all-distinct acc slots (no RAW)
            #pragma unroll
            for (int nb = 0; nb < 8; nb++) {
                #pragma unroll
                for (int mf = 0; mf < 2; mf++) {
                    MMA16816(acc[mf][nb * 2 + 0], ah[mf], bh[nb][0], bh[nb][2]);
                    MMA16816(acc[mf][nb * 2 + 1], ah[mf], bh[nb][1], bh[nb][3]);
                }
            }
            // Pass 2: al sweep -- same slots revisited 32 issues later
            #pragma unroll
            for (int nb = 0; nb < 8; nb++) {
                #pragma unroll
                for (int mf = 0; mf < 2; mf++) {
                    MMA16816(acc[mf][nb * 2 + 0], al[mf], bh[nb][0], bh[nb][2]);
                    MMA16816(acc[mf][nb * 2 + 1], al[mf], bh[nb][1], bh[nb][3]);
                }
            }
        }
        if (kc + 3 < NK) load_stage(kc + 3, (kc + 3) & 3);
        else             CP_COMMIT();
    }

    // Epilogue
    const long long zC = zb * sC;
    const int tr = lid >> 2;
    const int tc = (lid & 3) * 2;
    #pragma unroll
    for (int mf = 0; mf < 2; mf++) {
        #pragma unroll
        for (int nf = 0; nf < 16; nf++) {
            int gn = col0 + wn * 128 + nf * 8 + tc;
            #pragma unroll
            for (int half = 0; half < 2; half++) {
                int gm = row0 + wm * 32 + mf * 16 + tr + half * 8;
                float v0 = acc[mf][nf][half * 2 + 0] * alpha;
                float v1 = acc[mf][nf][half * 2 + 1] * alpha;
                long long o = zC + (long long)gm * N + gn;
                if (OUT_MODE == 0) {
                    *reinterpret_cast<float2*>(&Cf[o]) = make_float2(v0, v1);
                } else if (OUT_MODE == 1) {
                    __half h0 = __float2half_rn(v0), h1 = __float2half_rn(v1);
                    __half l0 = __float2half_rn(v0 - __half2float(h0));
                    __half l1 = __float2half_rn(v1 - __half2float(h1));
                    *reinterpret_cast<__half2*>(&Chi[o]) = __halves2half2(h0, h1);
                    *reinterpret_cast<__half2*>(&Clo[o]) = __halves2half2(l0, l1);
                } else {
                    *reinterpret_cast<__half2*>(&Chi[o]) =
                        __halves2half2(__float2half_rn(v0), __float2half_rn(v1));
                }
            }
        }
    }
}

// ---------------- host ----------------
extern "C" void kernel_launch(void* const* d_in, const int* in_sizes, int n_in,
                              void* d_out, int out_size)
{
    const float* query = (const float*)d_in[0];
    const float* key   = (const float*)d_in[1];
    const float* value = (const float*)d_in[2];
    const float* QW    = (const float*)d_in[3];
    const float* KW    = (const float*)d_in[4];
    const float* VW    = (const float*)d_in[5];
    float* out = (float*)d_out;

    cudaFuncSetAttribute(tc_gemm<0>, cudaFuncAttributeMaxDynamicSharedMemorySize, GEMM_SMEM);
    cudaFuncSetAttribute(tc_gemm<1>, cudaFuncAttributeMaxDynamicSharedMemorySize, GEMM_SMEM);
    cudaFuncSetAttribute(tc_gemm<2>, cudaFuncAttributeMaxDynamicSharedMemorySize, GEMM_SMEM);

    __half *qin_h, *qin_l, *kin_h, *kin_l, *vin_h, *vin_l;
    __half *wq_h, *wk_h, *wv_h;
    __half *q_h, *q_l, *k_h, *vt_h, *at_h, *at_l;
    float *vproj, *sc;
    cudaGetSymbolAddress((void**)&qin_h, g_qin_hi); cudaGetSymbolAddress((void**)&qin_l, g_qin_lo);
    cudaGetSymbolAddress((void**)&kin_h, g_kin_hi); cudaGetSymbolAddress((void**)&kin_l, g_kin_lo);
    cudaGetSymbolAddress((void**)&vin_h, g_vin_hi); cudaGetSymbolAddress((void**)&vin_l, g_vin_lo);
    cudaGetSymbolAddress((void**)&wq_h,  g_wq_hi);
    cudaGetSymbolAddress((void**)&wk_h,  g_wk_hi);
    cudaGetSymbolAddress((void**)&wv_h,  g_wv_hi);
    cudaGetSymbolAddress((void**)&q_h,   g_q_hi);   cudaGetSymbolAddress((void**)&q_l,   g_q_lo);
    cudaGetSymbolAddress((void**)&k_h,   g_k_hi);
    cudaGetSymbolAddress((void**)&vt_h,  g_vt_hi);
    cudaGetSymbolAddress((void**)&at_h,  g_at_hi);  cudaGetSymbolAddress((void**)&at_l,  g_at_lo);
    cudaGetSymbolAddress((void**)&vproj, g_vproj);
    cudaGetSymbolAddress((void**)&sc,    g_sc);

    const float scale = 1.0f / 32.0f;   // 1/sqrt(1024)

    // 1. split inputs (A-side: hi+lo); convert weights (B-side: hi only)
    {
        int n4 = MM * EE / 4;
        split_kernel<<<n4 / 256, 256>>>((const float4*)query, (ushort4*)qin_h, (ushort4*)qin_l, n4);
        split_kernel<<<n4 / 256, 256>>>((const float4*)key,   (ushort4*)kin_h, (ushort4*)kin_l, n4);
        split_kernel<<<n4 / 256, 256>>>((const float4*)value, (ushort4*)vin_h, (ushort4*)vin_l, n4);
        int w4 = EE * EE / 4;
        conv_kernel<<<w4 / 256, 256>>>((const float4*)QW, (ushort4*)wq_h, w4);
        conv_kernel<<<w4 / 256, 256>>>((const float4*)KW, (ushort4*)wk_h, w4);
        conv_kernel<<<w4 / 256, 256>>>((const float4*)VW, (ushort4*)wv_h, w4);
    }

    // 2. projections
    {
        dim3 grid(EE / 256, MM / 128, 1);
        tc_gemm<1><<<grid, 256, GEMM_SMEM>>>(qin_h, qin_l, wq_h, nullptr, q_h, q_l,
                                             MM, EE, EE, 0, 0, 0, 1.0f);
        tc_gemm<2><<<grid, 256, GEMM_SMEM>>>(kin_h, kin_l, wk_h, nullptr, k_h, nullptr,
                                             MM, EE, EE, 0, 0, 0, 1.0f);
        tc_gemm<0><<<grid, 256, GEMM_SMEM>>>(vin_h, vin_l, wv_h, vproj, nullptr, nullptr,
                                             MM, EE, EE, 0, 0, 0, 1.0f);
    }
    {
        dim3 grid(EE / 32, SS / 32, BB);
        tsplit_kernel<<<grid, dim3(32, 8)>>>(vproj, vt_h);
    }

    // 3. scores = (q @ k^T) * scale
    {
        dim3 grid(SS / 256, SS / 128, BB);
        tc_gemm<0><<<grid, 256, GEMM_SMEM>>>(q_h, q_l, k_h, sc, nullptr, nullptr,
                                             SS, SS, EE,
                                             (long long)SS * EE, (long long)SS * EE,
                                             (long long)SS * SS, scale);
    }

    // 4. softmax -> split fp16 attn (A-side: hi+lo)
    softmax_split_kernel<<<BB * SS, 256>>>(sc, at_h, at_l);

    // 5. out = attn @ v  (B = v^T hi, K-major)
    {
        dim3 grid(EE / 256, SS / 128, BB);
        tc_gemm<0><<<grid, 256, GEMM_SMEM>>>(at_h, at_l, vt_h, out, nullptr, nullptr,
                                             SS, EE, SS,
                                             (long long)SS * SS, (long long)EE * SS,
                                             (long long)SS * EE, 1.0f);
    }
}

// round 10
// speedup vs baseline: 1.2210x; 1.2210x over previous
#include <cuda_runtime.h>
#include <cuda_fp16.h>
#include <cstdint>

#define BB 4
#define SS 2048
#define EE 1024
#define MM (BB*SS)

// ---------------- PTX helpers (baseline ISA only; no sm_103a-accel features) ----------------
__device__ __forceinline__ uint32_t smem_u32(const void* p) {
    uint32_t a;
    asm("{ .reg .u64 t; cvta.to.shared.u64 t, %1; cvt.u32.u64 %0, t; }" : "=r"(a) : "l"(p));
    return a;
}

#define LDSM4(r0, r1, r2, r3, addr) \
    asm volatile("ldmatrix.sync.aligned.m8n8.x4.shared.b16 {%0,%1,%2,%3}, [%4];" \
        : "=r"(r0), "=r"(r1), "=r"(r2), "=r"(r3) : "r"(addr))

#define MMA16816(d, a, b0, b1) \
    asm volatile("mma.sync.aligned.m16n8k16.row.col.f32.f16.f16.f32 " \
        "{%0,%1,%2,%3}, {%4,%5,%6,%7}, {%8,%9}, {%0,%1,%2,%3};" \
        : "+f"((d)[0]), "+f"((d)[1]), "+f"((d)[2]), "+f"((d)[3]) \
        : "r"((a)[0]), "r"((a)[1]), "r"((a)[2]), "r"((a)[3]), "r"(b0), "r"(b1))

#define CP_ASYNC16(saddr, gptr) \
    asm volatile("cp.async.cg.shared.global [%0], [%1], 16;" :: "r"(saddr), "l"(gptr) : "memory")
#define CP_COMMIT() asm volatile("cp.async.commit_group;" ::: "memory")
#define CP_WAIT2()  asm volatile("cp.async.wait_group 2;" ::: "memory")

// ---------------- scratch (device globals, allocation-free) ----------------
__device__ __align__(1024) __half g_qin_hi[(size_t)MM * EE], g_qin_lo[(size_t)MM * EE];
__device__ __align__(1024) __half g_kin_hi[(size_t)MM * EE], g_kin_lo[(size_t)MM * EE];
__device__ __align__(1024) __half g_vin_hi[(size_t)MM * EE];
__device__ __align__(1024) __half g_wq_hi[(size_t)EE * EE];
__device__ __align__(1024) __half g_wk_hi[(size_t)EE * EE];
__device__ __align__(1024) __half g_wv_hi[(size_t)EE * EE];
__device__ __align__(1024) __half g_q_hi[(size_t)MM * EE], g_q_lo[(size_t)MM * EE];
__device__ __align__(1024) __half g_k_hi[(size_t)MM * EE];
__device__ __align__(1024) float  g_vproj[(size_t)MM * EE];
__device__ __align__(1024) __half g_vt_hi[(size_t)MM * EE];
__device__ __align__(1024) float  g_sc[(size_t)BB * SS * SS];
__device__ __align__(1024) __half g_at_hi[(size_t)BB * SS * SS];

// ---------------- split / convert / transpose / softmax ----------------
__global__ void __launch_bounds__(256)
split_kernel(const float4* __restrict__ x, ushort4* __restrict__ hi, ushort4* __restrict__ lo, int n4)
{
    int i = blockIdx.x * blockDim.x + threadIdx.x;
    if (i >= n4) return;
    float4 v = x[i];
    __half hx = __float2half_rn(v.x), hy = __float2half_rn(v.y);
    __half hz = __float2half_rn(v.z), hw = __float2half_rn(v.w);
    ushort4 h, l;
    h.x = __half_as_ushort(hx); h.y = __half_as_ushort(hy);
    h.z = __half_as_ushort(hz); h.w = __half_as_ushort(hw);
    l.x = __half_as_ushort(__float2half_rn(v.x - __half2float(hx)));
    l.y = __half_as_ushort(__float2half_rn(v.y - __half2float(hy)));
    l.z = __half_as_ushort(__float2half_rn(v.z - __half2float(hz)));
    l.w = __half_as_ushort(__float2half_rn(v.w - __half2float(hw)));
    hi[i] = h; lo[i] = l;
}

__global__ void __launch_bounds__(256)
conv_kernel(const float4* __restrict__ x, ushort4* __restrict__ hi, int n4)
{
    int i = blockIdx.x * blockDim.x + threadIdx.x;
    if (i >= n4) return;
    float4 v = x[i];
    ushort4 h;
    h.x = __half_as_ushort(__float2half_rn(v.x));
    h.y = __half_as_ushort(__float2half_rn(v.y));
    h.z = __half_as_ushort(__float2half_rn(v.z));
    h.w = __half_as_ushort(__float2half_rn(v.w));
    hi[i] = h;
}

// transpose: v [BB][SS][EE] fp32 -> vt hi [BB][EE][SS] fp16
__global__ void __launch_bounds__(256)
tsplit_kernel(const float* __restrict__ v, __half* __restrict__ thi)
{
    __shared__ float tile[32][33];
    int b = blockIdx.z;
    int e0 = blockIdx.x * 32, s0 = blockIdx.y * 32;
    int tx = threadIdx.x, ty = threadIdx.y;  // 32 x 8
    #pragma unroll
    for (int k = 0; k < 32; k += 8)
        tile[ty + k][tx] = v[((long long)b * SS + s0 + ty + k) * EE + e0 + tx];
    __syncthreads();
    #pragma unroll
    for (int k = 0; k < 32; k += 8) {
        float val = tile[tx][ty + k];
        long long o = ((long long)b * EE + e0 + ty + k) * SS + s0 + tx;
        thi[o] = __float2half_rn(val);
    }
}

__global__ void __launch_bounds__(256)
softmax_split_kernel(const float* __restrict__ sc, __half* __restrict__ ahi)
{
    const float* p = sc + (long long)blockIdx.x * SS;
    long long obase = (long long)blockIdx.x * SS;
    const int t = threadIdx.x;
    __shared__ float red[8];

    float vals[SS / 256];
    float m = -1e30f;
    #pragma unroll
    for (int i = 0; i < SS / 256; i++) { vals[i] = p[t + i * 256]; m = fmaxf(m, vals[i]); }
    #pragma unroll
    for (int o = 16; o > 0; o >>= 1) m = fmaxf(m, __shfl_xor_sync(0xFFFFFFFFu, m, o));
    if ((t & 31) == 0) red[t >> 5] = m;
    __syncthreads();
    float mm = red[0];
    #pragma unroll
    for (int i = 1; i < 8; i++) mm = fmaxf(mm, red[i]);
    __syncthreads();

    float s = 0.0f;
    #pragma unroll
    for (int i = 0; i < SS / 256; i++) { vals[i] = __expf(vals[i] - mm); s += vals[i]; }
    #pragma unroll
    for (int o = 16; o > 0; o >>= 1) s += __shfl_xor_sync(0xFFFFFFFFu, s, o);
    if ((t & 31) == 0) red[t >> 5] = s;
    __syncthreads();
    float ssum = 0.0f;
    #pragma unroll
    for (int i = 0; i < 8; i++) ssum += red[i];
    float inv = 1.0f / ssum;

    #pragma unroll
    for (int i = 0; i < SS / 256; i++)
        ahi[obase + t + i * 256] = __float2half_rn(vals[i] * inv);
}

// ---------------- split-fp16 tensor-core GEMM ----------------
// SPLIT_A=true : C = alpha * (Ah+Al)[M,K] * Bh[N,K]^T  (2-pass MMA)
// SPLIT_A=false: C = alpha * Ah[M,K] * Bh[N,K]^T       (1-pass MMA)
// CTA tile 128x256, K-chunk 32, 8 warps (warp tile 32x128), 4-buffer cp.async.
static constexpr int TILE_A  = 128 * 80;               // 10240 B (A tile: 128 rows)
static constexpr int TILE_Bb = 256 * 80;               // 20480 B (B tile: 256 rows)
static constexpr int STAGE_B = 2 * TILE_A + TILE_Bb;   // 40960 B: Ah, Al, Bh
static constexpr int NSTAGE  = 4;
static constexpr int GEMM_SMEM = NSTAGE * STAGE_B;     // 163840

template <int OUT_MODE, bool SPLIT_A>   // OUT: 0 fp32 ; 1 split fp16 ; 2 fp16 hi
__global__ void __launch_bounds__(256, 1)
tc_gemm(const __half* __restrict__ Ahi, const __half* __restrict__ Alo,
        const __half* __restrict__ Bhi,
        float* __restrict__ Cf, __half* __restrict__ Chi, __half* __restrict__ Clo,
        int M, int N, int K, long long sA, long long sB, long long sC, float alpha)
{
    extern __shared__ char smem[];
    const uint32_t sbase = smem_u32(smem);
    const int tid = threadIdx.x;
    const int wid = tid >> 5;
    const int lid = tid & 31;
    const int wm = wid & 3;        // warp m block (32 rows)
    const int wn = wid >> 2;       // warp n block (128 cols)

    const int row0 = blockIdx.y * 128;
    const int col0 = blockIdx.x * 256;
    const long long zb = blockIdx.z;
    const __half* A0 = Ahi + zb * sA;
    const __half* A1 = SPLIT_A ? (Alo + zb * sA) : nullptr;
    const __half* B0 = Bhi + zb * sB;

    const int NK = K >> 5;  // K-chunks of 32

    auto load_stage = [&](int kc, int st) {
        const uint32_t stb = sbase + (uint32_t)st * STAGE_B;
        #pragma unroll
        for (int j = 0; j < 8; j++) {
            int i = tid + j * 256;      // 0..2047
            const __half* g;
            uint32_t s;
            if (i < 1024) {             // Ah (0..511), Al (512..1023)
                int tile = i >> 9;
                if (!SPLIT_A && tile == 1) continue;
                int idx = i & 511;
                int row = idx >> 2, ch = idx & 3;
                const __half* src = (tile == 0) ? A0 : A1;
                g = src + (long long)(row0 + row) * K + kc * 32 + ch * 8;
                s = stb + (uint32_t)(tile * TILE_A + row * 80 + ch * 16);
            } else {                    // Bh: 256 rows
                int idx = i - 1024;
                int row = idx >> 2, ch = idx & 3;
                g = B0 + (long long)(col0 + row) * K + kc * 32 + ch * 8;
                s = stb + (uint32_t)(2 * TILE_A + row * 80 + ch * 16);
            }
            CP_ASYNC16(s, __cvta_generic_to_global((const void*)g));
        }
        CP_COMMIT();
    };

    load_stage(0, 0);
    load_stage(1, 1);
    load_stage(2, 2);

    float acc[2][16][4];
    #pragma unroll
    for (int a = 0; a < 2; a++)
        #pragma unroll
        for (int b = 0; b < 16; b++)
            #pragma unroll
            for (int c = 0; c < 4; c++) acc[a][b][c] = 0.0f;

    const int lrow = lid & 15;
    const int lch  = lid >> 4;

    for (int kc = 0; kc < NK; kc++) {
        CP_WAIT2();
        __syncthreads();

        const int st = kc & 3;
        const uint32_t stb = sbase + (uint32_t)st * STAGE_B;
        #pragma unroll
        for (int ks = 0; ks < 2; ks++) {
            const uint32_t choff = (uint32_t)((ks * 2 + lch) * 16);
            uint32_t ah[2][4], al[2][4];
            #pragma unroll
            for (int mf = 0; mf < 2; mf++) {
                uint32_t ra = stb + (uint32_t)((wm * 32 + mf * 16 + lrow) * 80) + choff;
                LDSM4(ah[mf][0], ah[mf][1], ah[mf][2], ah[mf][3], ra);
                if (SPLIT_A) LDSM4(al[mf][0], al[mf][1], al[mf][2], al[mf][3], ra + TILE_A);
            }
            uint32_t bh[8][4];
            #pragma unroll
            for (int nb = 0; nb < 8; nb++) {
                uint32_t rb = stb + (uint32_t)(2 * TILE_A + (wn * 128 + nb * 16 + lrow) * 80) + choff;
                LDSM4(bh[nb][0], bh[nb][1], bh[nb][2], bh[nb][3], rb);
            }
            #pragma unroll
            for (int nb = 0; nb < 8; nb++) {
                #pragma unroll
                for (int mf = 0; mf < 2; mf++) {
                    MMA16816(acc[mf][nb * 2 + 0], ah[mf], bh[nb][0], bh[nb][2]);
                    MMA16816(acc[mf][nb * 2 + 1], ah[mf], bh[nb][1], bh[nb][3]);
                }
            }
            if (SPLIT_A) {
                #pragma unroll
                for (int nb = 0; nb < 8; nb++) {
                    #pragma unroll
                    for (int mf = 0; mf < 2; mf++) {
                        MMA16816(acc[mf][nb * 2 + 0], al[mf], bh[nb][0], bh[nb][2]);
                        MMA16816(acc[mf][nb * 2 + 1], al[mf], bh[nb][1], bh[nb][3]);
                    }
                }
            }
        }
        if (kc + 3 < NK) load_stage(kc + 3, (kc + 3) & 3);
        else             CP_COMMIT();
    }

    // Epilogue
    const long long zC = zb * sC;
    const int tr = lid >> 2;
    const int tc = (lid & 3) * 2;
    #pragma unroll
    for (int mf = 0; mf < 2; mf++) {
        #pragma unroll
        for (int nf = 0; nf < 16; nf++) {
            int gn = col0 + wn * 128 + nf * 8 + tc;
            #pragma unroll
            for (int half = 0; half < 2; half++) {
                int gm = row0 + wm * 32 + mf * 16 + tr + half * 8;
                float v0 = acc[mf][nf][half * 2 + 0] * alpha;
                float v1 = acc[mf][nf][half * 2 + 1] * alpha;
                long long o = zC + (long long)gm * N + gn;
                if (OUT_MODE == 0) {
                    *reinterpret_cast<float2*>(&Cf[o]) = make_float2(v0, v1);
                } else if (OUT_MODE == 1) {
                    __half h0 = __float2half_rn(v0), h1 = __float2half_rn(v1);
                    __half l0 = __float2half_rn(v0 - __half2float(h0));
                    __half l1 = __float2half_rn(v1 - __half2float(h1));
                    *reinterpret_cast<__half2*>(&Chi[o]) = __halves2half2(h0, h1);
                    *reinterpret_cast<__half2*>(&Clo[o]) = __halves2half2(l0, l1);
                } else {
                    *reinterpret_cast<__half2*>(&Chi[o]) =
                        __halves2half2(__float2half_rn(v0), __float2half_rn(v1));
                }
            }
        }
    }
}

// ---------------- host ----------------
extern "C" void kernel_launch(void* const* d_in, const int* in_sizes, int n_in,
                              void* d_out, int out_size)
{
    const float* query = (const float*)d_in[0];
    const float* key   = (const float*)d_in[1];
    const float* value = (const float*)d_in[2];
    const float* QW    = (const float*)d_in[3];
    const float* KW    = (const float*)d_in[4];
    const float* VW    = (const float*)d_in[5];
    float* out = (float*)d_out;

    cudaFuncSetAttribute(tc_gemm<0, true>,  cudaFuncAttributeMaxDynamicSharedMemorySize, GEMM_SMEM);
    cudaFuncSetAttribute(tc_gemm<1, true>,  cudaFuncAttributeMaxDynamicSharedMemorySize, GEMM_SMEM);
    cudaFuncSetAttribute(tc_gemm<2, true>,  cudaFuncAttributeMaxDynamicSharedMemorySize, GEMM_SMEM);
    cudaFuncSetAttribute(tc_gemm<0, false>, cudaFuncAttributeMaxDynamicSharedMemorySize, GEMM_SMEM);

    __half *qin_h, *qin_l, *kin_h, *kin_l, *vin_h;
    __half *wq_h, *wk_h, *wv_h;
    __half *q_h, *q_l, *k_h, *vt_h, *at_h;
    float *vproj, *sc;
    cudaGetSymbolAddress((void**)&qin_h, g_qin_hi); cudaGetSymbolAddress((void**)&qin_l, g_qin_lo);
    cudaGetSymbolAddress((void**)&kin_h, g_kin_hi); cudaGetSymbolAddress((void**)&kin_l, g_kin_lo);
    cudaGetSymbolAddress((void**)&vin_h, g_vin_hi);
    cudaGetSymbolAddress((void**)&wq_h,  g_wq_hi);
    cudaGetSymbolAddress((void**)&wk_h,  g_wk_hi);
    cudaGetSymbolAddress((void**)&wv_h,  g_wv_hi);
    cudaGetSymbolAddress((void**)&q_h,   g_q_hi);   cudaGetSymbolAddress((void**)&q_l,   g_q_lo);
    cudaGetSymbolAddress((void**)&k_h,   g_k_hi);
    cudaGetSymbolAddress((void**)&vt_h,  g_vt_hi);
    cudaGetSymbolAddress((void**)&at_h,  g_at_hi);
    cudaGetSymbolAddress((void**)&vproj, g_vproj);
    cudaGetSymbolAddress((void**)&sc,    g_sc);

    const float scale = 1.0f / 32.0f;   // 1/sqrt(1024)

    // 1. preprocess: q,k inputs split (hi+lo); v input + weights hi only
    {
        int n4 = MM * EE / 4;
        split_kernel<<<n4 / 256, 256>>>((const float4*)query, (ushort4*)qin_h, (ushort4*)qin_l, n4);
        split_kernel<<<n4 / 256, 256>>>((const float4*)key,   (ushort4*)kin_h, (ushort4*)kin_l, n4);
        conv_kernel<<<n4 / 256, 256>>>((const float4*)value,  (ushort4*)vin_h, n4);
        int w4 = EE * EE / 4;
        conv_kernel<<<w4 / 256, 256>>>((const float4*)QW, (ushort4*)wq_h, w4);
        conv_kernel<<<w4 / 256, 256>>>((const float4*)KW, (ushort4*)wk_h, w4);
        conv_kernel<<<w4 / 256, 256>>>((const float4*)VW, (ushort4*)wv_h, w4);
    }

    // 2. projections: q 2-pass -> split out; k 2-pass -> hi out; v 1-pass -> fp32
    {
        dim3 grid(EE / 256, MM / 128, 1);
        tc_gemm<1, true ><<<grid, 256, GEMM_SMEM>>>(qin_h, qin_l, wq_h, nullptr, q_h, q_l,
                                                    MM, EE, EE, 0, 0, 0, 1.0f);
        tc_gemm<2, true ><<<grid, 256, GEMM_SMEM>>>(kin_h, kin_l, wk_h, nullptr, k_h, nullptr,
                                                    MM, EE, EE, 0, 0, 0, 1.0f);
        tc_gemm<0, false><<<grid, 256, GEMM_SMEM>>>(vin_h, nullptr, wv_h, vproj, nullptr, nullptr,
                                                    MM, EE, EE, 0, 0, 0, 1.0f);
    }
    {
        dim3 grid(EE / 32, SS / 32, BB);
        tsplit_kernel<<<grid, dim3(32, 8)>>>(vproj, vt_h);
    }

    // 3. scores = (q @ k^T) * scale  (q split: 2-pass)
    {
        dim3 grid(SS / 256, SS / 128, BB);
        tc_gemm<0, true><<<grid, 256, GEMM_SMEM>>>(q_h, q_l, k_h, sc, nullptr, nullptr,
                                                   SS, SS, EE,
                                                   (long long)SS * EE, (long long)SS * EE,
                                                   (long long)SS * SS, scale);
    }

    // 4. softmax -> fp16 attn (hi only)
    softmax_split_kernel<<<BB * SS, 256>>>(sc, at_h);

    // 5. out = attn @ v  (1-pass)
    {
        dim3 grid(EE / 256, SS / 128, BB);
        tc_gemm<0, false><<<grid, 256, GEMM_SMEM>>>(at_h, nullptr, vt_h, out, nullptr, nullptr,
                                                    SS, EE, SS,
                                                    (long long)SS * SS, (long long)EE * SS,
                                                    (long long)SS * EE, 1.0f);
    }
}

// round 13
// speedup vs baseline: 1.2948x; 1.0604x over previous
#include <cuda_runtime.h>
#include <cuda_fp16.h>
#include <cstdint>

#define BB 4
#define SS 2048
#define EE 1024
#define MM (BB*SS)

// ---------------- PTX helpers (baseline ISA only; no sm_103a-accel features) ----------------
__device__ __forceinline__ uint32_t smem_u32(const void* p) {
    uint32_t a;
    asm("{ .reg .u64 t; cvta.to.shared.u64 t, %1; cvt.u32.u64 %0, t; }" : "=r"(a) : "l"(p));
    return a;
}

#define LDSM4(r0, r1, r2, r3, addr) \
    asm volatile("ldmatrix.sync.aligned.m8n8.x4.shared.b16 {%0,%1,%2,%3}, [%4];" \
        : "=r"(r0), "=r"(r1), "=r"(r2), "=r"(r3) : "r"(addr))

#define MMA16816(d, a, b0, b1) \
    asm volatile("mma.sync.aligned.m16n8k16.row.col.f32.f16.f16.f32 " \
        "{%0,%1,%2,%3}, {%4,%5,%6,%7}, {%8,%9}, {%0,%1,%2,%3};" \
        : "+f"((d)[0]), "+f"((d)[1]), "+f"((d)[2]), "+f"((d)[3]) \
        : "r"((a)[0]), "r"((a)[1]), "r"((a)[2]), "r"((a)[3]), "r"(b0), "r"(b1))

#define CP_ASYNC16(saddr, gptr) \
    asm volatile("cp.async.cg.shared.global [%0], [%1], 16;" :: "r"(saddr), "l"(gptr) : "memory")
#define CP_COMMIT() asm volatile("cp.async.commit_group;" ::: "memory")
#define CP_WAIT1()  asm volatile("cp.async.wait_group 1;" ::: "memory")

// ---------------- scratch (device globals, allocation-free) ----------------
__device__ __align__(1024) __half g_qin_hi[(size_t)MM * EE], g_qin_lo[(size_t)MM * EE];
__device__ __align__(1024) __half g_kin_hi[(size_t)MM * EE], g_kin_lo[(size_t)MM * EE];
__device__ __align__(1024) __half g_vin_hi[(size_t)MM * EE];
__device__ __align__(1024) __half g_wq_hi[(size_t)EE * EE];
__device__ __align__(1024) __half g_wk_hi[(size_t)EE * EE];
__device__ __align__(1024) __half g_wv_hi[(size_t)EE * EE];
__device__ __align__(1024) __half g_q_hi[(size_t)MM * EE], g_q_lo[(size_t)MM * EE];
__device__ __align__(1024) __half g_k_hi[(size_t)MM * EE];
__device__ __align__(1024) float  g_vproj[(size_t)MM * EE];
__device__ __align__(1024) __half g_vt_hi[(size_t)MM * EE];
__device__ __align__(1024) float  g_sc[(size_t)BB * SS * SS];
__device__ __align__(1024) __half g_at_hi[(size_t)BB * SS * SS];

// ---------------- split / convert / transpose / softmax ----------------
__global__ void __launch_bounds__(256)
split_kernel(const float4* __restrict__ x, ushort4* __restrict__ hi, ushort4* __restrict__ lo, int n4)
{
    int i = blockIdx.x * blockDim.x + threadIdx.x;
    if (i >= n4) return;
    float4 v = x[i];
    __half hx = __float2half_rn(v.x), hy = __float2half_rn(v.y);
    __half hz = __float2half_rn(v.z), hw = __float2half_rn(v.w);
    ushort4 h, l;
    h.x = __half_as_ushort(hx); h.y = __half_as_ushort(hy);
    h.z = __half_as_ushort(hz); h.w = __half_as_ushort(hw);
    l.x = __half_as_ushort(__float2half_rn(v.x - __half2float(hx)));
    l.y = __half_as_ushort(__float2half_rn(v.y - __half2float(hy)));
    l.z = __half_as_ushort(__float2half_rn(v.z - __half2float(hz)));
    l.w = __half_as_ushort(__float2half_rn(v.w - __half2float(hw)));
    hi[i] = h; lo[i] = l;
}

__global__ void __launch_bounds__(256)
conv_kernel(const float4* __restrict__ x, ushort4* __restrict__ hi, int n4)
{
    int i = blockIdx.x * blockDim.x + threadIdx.x;
    if (i >= n4) return;
    float4 v = x[i];
    ushort4 h;
    h.x = __half_as_ushort(__float2half_rn(v.x));
    h.y = __half_as_ushort(__float2half_rn(v.y));
    h.z = __half_as_ushort(__float2half_rn(v.z));
    h.w = __half_as_ushort(__float2half_rn(v.w));
    hi[i] = h;
}

// transpose: v [BB][SS][EE] fp32 -> vt hi [BB][EE][SS] fp16
__global__ void __launch_bounds__(256)
tsplit_kernel(const float* __restrict__ v, __half* __restrict__ thi)
{
    __shared__ float tile[32][33];
    int b = blockIdx.z;
    int e0 = blockIdx.x * 32, s0 = blockIdx.y * 32;
    int tx = threadIdx.x, ty = threadIdx.y;  // 32 x 8
    #pragma unroll
    for (int k = 0; k < 32; k += 8)
        tile[ty + k][tx] = v[((long long)b * SS + s0 + ty + k) * EE + e0 + tx];
    __syncthreads();
    #pragma unroll
    for (int k = 0; k < 32; k += 8) {
        float val = tile[tx][ty + k];
        long long o = ((long long)b * EE + e0 + ty + k) * SS + s0 + tx;
        thi[o] = __float2half_rn(val);
    }
}

__global__ void __launch_bounds__(256)
softmax_split_kernel(const float* __restrict__ sc, __half* __restrict__ ahi)
{
    const float* p = sc + (long long)blockIdx.x * SS;
    long long obase = (long long)blockIdx.x * SS;
    const int t = threadIdx.x;
    __shared__ float red[8];

    float vals[SS / 256];
    float m = -1e30f;
    #pragma unroll
    for (int i = 0; i < SS / 256; i++) { vals[i] = p[t + i * 256]; m = fmaxf(m, vals[i]); }
    #pragma unroll
    for (int o = 16; o > 0; o >>= 1) m = fmaxf(m, __shfl_xor_sync(0xFFFFFFFFu, m, o));
    if ((t & 31) == 0) red[t >> 5] = m;
    __syncthreads();
    float mm = red[0];
    #pragma unroll
    for (int i = 1; i < 8; i++) mm = fmaxf(mm, red[i]);
    __syncthreads();

    float s = 0.0f;
    #pragma unroll
    for (int i = 0; i < SS / 256; i++) { vals[i] = __expf(vals[i] - mm); s += vals[i]; }
    #pragma unroll
    for (int o = 16; o > 0; o >>= 1) s += __shfl_xor_sync(0xFFFFFFFFu, s, o);
    if ((t & 31) == 0) red[t >> 5] = s;
    __syncthreads();
    float ssum = 0.0f;
    #pragma unroll
    for (int i = 0; i < 8; i++) ssum += red[i];
    float inv = 1.0f / ssum;

    #pragma unroll
    for (int i = 0; i < SS / 256; i++)
        ahi[obase + t + i * 256] = __float2half_rn(vals[i] * inv);
}

// ---------------- split-fp16 tensor-core GEMM ----------------
// SPLIT_A=true : C = alpha * (Ah+Al)[M,K] * Bh[N,K]^T  (2-pass MMA)
// SPLIT_A=false: C = alpha * Ah[M,K] * Bh[N,K]^T       (1-pass MMA)
// CTA tile 128x128, K-chunk 32, 8 warps (warp tile 32x64).
// 3-buffer / 2-ahead cp.async pipeline: load kc+2 at end of iter kc into the
// buffer consumed at kc-1 (fenced by this iteration's __syncthreads()).
// 92KB smem/CTA -> 2 CTAs/SM (4 warps/SMSP) for latency hiding.
static constexpr int TILE_A  = 128 * 80;               // 10240 B per 128-row tile
static constexpr int STAGE_B = 3 * TILE_A;             // 30720 B: Ah, Al, Bh
static constexpr int NSTAGE  = 3;
static constexpr int GEMM_SMEM = NSTAGE * STAGE_B;     // 92160

template <int OUT_MODE, bool SPLIT_A>   // OUT: 0 fp32 ; 1 split fp16 ; 2 fp16 hi
__global__ void __launch_bounds__(256, 2)
tc_gemm(const __half* __restrict__ Ahi, const __half* __restrict__ Alo,
        const __half* __restrict__ Bhi,
        float* __restrict__ Cf, __half* __restrict__ Chi, __half* __restrict__ Clo,
        int M, int N, int K, long long sA, long long sB, long long sC, float alpha)
{
    extern __shared__ char smem[];
    const uint32_t sbase = smem_u32(smem);
    const int tid = threadIdx.x;
    const int wid = tid >> 5;
    const int lid = tid & 31;
    const int wm = wid & 3;        // warp m block (32 rows)
    const int wn = wid >> 2;       // warp n block (64 cols)

    const int row0 = blockIdx.y * 128;
    const int col0 = blockIdx.x * 128;
    const long long zb = blockIdx.z;
    const __half* A0 = Ahi + zb * sA;
    const __half* A1 = SPLIT_A ? (Alo + zb * sA) : nullptr;
    const __half* B0 = Bhi + zb * sB;

    const int NK = K >> 5;  // K-chunks of 32

    auto load_stage = [&](int kc, int st) {
        const uint32_t stb = sbase + (uint32_t)st * STAGE_B;
        #pragma unroll
        for (int j = 0; j < 6; j++) {
            int i = tid + j * 256;      // 0..1535
            int tile = i >> 9;          // 0 Ah, 1 Al, 2 Bh
            if (!SPLIT_A && tile == 1) continue;
            int idx = i & 511;
            int row = idx >> 2, ch = idx & 3;
            const __half* src = (tile == 0) ? A0 : (tile == 1) ? A1 : B0;
            int base = (tile < 2) ? row0 : col0;
            const __half* g = src + (long long)(base + row) * K + kc * 32 + ch * 8;
            uint32_t s = stb + (uint32_t)(tile * TILE_A + row * 80 + ch * 16);
            CP_ASYNC16(s, __cvta_generic_to_global((const void*)g));
        }
        CP_COMMIT();
    };

    // 2-ahead preload into buffers 0,1
    load_stage(0, 0);
    load_stage(1, 1);

    float acc[2][8][4];
    #pragma unroll
    for (int a = 0; a < 2; a++)
        #pragma unroll
        for (int b = 0; b < 8; b++)
            #pragma unroll
            for (int c = 0; c < 4; c++) acc[a][b][c] = 0.0f;

    const int lrow = lid & 15;
    const int lch  = lid >> 4;

    for (int kc = 0; kc < NK; kc++) {
        CP_WAIT1();            // stage kc's group complete (<=1 pending)
        __syncthreads();       // also fences: all warps done reading stage kc-1's buffer

        const int st = kc % 3;
        const uint32_t stb = sbase + (uint32_t)st * STAGE_B;
        #pragma unroll
        for (int ks = 0; ks < 2; ks++) {
            const uint32_t choff = (uint32_t)((ks * 2 + lch) * 16);
            uint32_t ah[2][4], al[2][4];
            #pragma unroll
            for (int mf = 0; mf < 2; mf++) {
                uint32_t ra = stb + (uint32_t)((wm * 32 + mf * 16 + lrow) * 80) + choff;
                LDSM4(ah[mf][0], ah[mf][1], ah[mf][2], ah[mf][3], ra);
                if (SPLIT_A) LDSM4(al[mf][0], al[mf][1], al[mf][2], al[mf][3], ra + TILE_A);
            }
            uint32_t bh[4][4];
            #pragma unroll
            for (int nb = 0; nb < 4; nb++) {
                uint32_t rb = stb + (uint32_t)(2 * TILE_A + (wn * 64 + nb * 16 + lrow) * 80) + choff;
                LDSM4(bh[nb][0], bh[nb][1], bh[nb][2], bh[nb][3], rb);
            }
            #pragma unroll
            for (int nb = 0; nb < 4; nb++) {
                #pragma unroll
                for (int mf = 0; mf < 2; mf++) {
                    MMA16816(acc[mf][nb * 2 + 0], ah[mf], bh[nb][0], bh[nb][2]);
                    MMA16816(acc[mf][nb * 2 + 1], ah[mf], bh[nb][1], bh[nb][3]);
                }
            }
            if (SPLIT_A) {
                #pragma unroll
                for (int nb = 0; nb < 4; nb++) {
                    #pragma unroll
                    for (int mf = 0; mf < 2; mf++) {
                        MMA16816(acc[mf][nb * 2 + 0], al[mf], bh[nb][0], bh[nb][2]);
                        MMA16816(acc[mf][nb * 2 + 1], al[mf], bh[nb][1], bh[nb][3]);
                    }
                }
            }
        }
        // load kc+2 into buffer (kc+2)%3: consumed at kc-1, fenced by this
        // iteration's __syncthreads(). One commit per iter (empty at tail).
        if (kc + 2 < NK) load_stage(kc + 2, (kc + 2) % 3);
        else             CP_COMMIT();
    }

    // Epilogue
    const long long zC = zb * sC;
    const int tr = lid >> 2;
    const int tc = (lid & 3) * 2;
    #pragma unroll
    for (int mf = 0; mf < 2; mf++) {
        #pragma unroll
        for (int nf = 0; nf < 8; nf++) {
            int gn = col0 + wn * 64 + nf * 8 + tc;
            #pragma unroll
            for (int half = 0; half < 2; half++) {
                int gm = row0 + wm * 32 + mf * 16 + tr + half * 8;
                float v0 = acc[mf][nf][half * 2 + 0] * alpha;
                float v1 = acc[mf][nf][half * 2 + 1] * alpha;
                long long o = zC + (long long)gm * N + gn;
                if (OUT_MODE == 0) {
                    *reinterpret_cast<float2*>(&Cf[o]) = make_float2(v0, v1);
                } else if (OUT_MODE == 1) {
                    __half h0 = __float2half_rn(v0), h1 = __float2half_rn(v1);
                    __half l0 = __float2half_rn(v0 - __half2float(h0));
                    __half l1 = __float2half_rn(v1 - __half2float(h1));
                    *reinterpret_cast<__half2*>(&Chi[o]) = __halves2half2(h0, h1);
                    *reinterpret_cast<__half2*>(&Clo[o]) = __halves2half2(l0, l1);
                } else {
                    *reinterpret_cast<__half2*>(&Chi[o]) =
                        __halves2half2(__float2half_rn(v0), __float2half_rn(v1));
                }
            }
        }
    }
}

// ---------------- host ----------------
extern "C" void kernel_launch(void* const* d_in, const int* in_sizes, int n_in,
                              void* d_out, int out_size)
{
    const float* query = (const float*)d_in[0];
    const float* key   = (const float*)d_in[1];
    const float* value = (const float*)d_in[2];
    const float* QW    = (const float*)d_in[3];
    const float* KW    = (const float*)d_in[4];
    const float* VW    = (const float*)d_in[5];
    float* out = (float*)d_out;

    cudaFuncSetAttribute(tc_gemm<0, true>,  cudaFuncAttributeMaxDynamicSharedMemorySize, GEMM_SMEM);
    cudaFuncSetAttribute(tc_gemm<1, true>,  cudaFuncAttributeMaxDynamicSharedMemorySize, GEMM_SMEM);
    cudaFuncSetAttribute(tc_gemm<2, true>,  cudaFuncAttributeMaxDynamicSharedMemorySize, GEMM_SMEM);
    cudaFuncSetAttribute(tc_gemm<0, false>, cudaFuncAttributeMaxDynamicSharedMemorySize, GEMM_SMEM);

    __half *qin_h, *qin_l, *kin_h, *kin_l, *vin_h;
    __half *wq_h, *wk_h, *wv_h;
    __half *q_h, *q_l, *k_h, *vt_h, *at_h;
    float *vproj, *sc;
    cudaGetSymbolAddress((void**)&qin_h, g_qin_hi); cudaGetSymbolAddress((void**)&qin_l, g_qin_lo);
    cudaGetSymbolAddress((void**)&kin_h, g_kin_hi); cudaGetSymbolAddress((void**)&kin_l, g_kin_lo);
    cudaGetSymbolAddress((void**)&vin_h, g_vin_hi);
    cudaGetSymbolAddress((void**)&wq_h,  g_wq_hi);
    cudaGetSymbolAddress((void**)&wk_h,  g_wk_hi);
    cudaGetSymbolAddress((void**)&wv_h,  g_wv_hi);
    cudaGetSymbolAddress((void**)&q_h,   g_q_hi);   cudaGetSymbolAddress((void**)&q_l,   g_q_lo);
    cudaGetSymbolAddress((void**)&k_h,   g_k_hi);
    cudaGetSymbolAddress((void**)&vt_h,  g_vt_hi);
    cudaGetSymbolAddress((void**)&at_h,  g_at_hi);
    cudaGetSymbolAddress((void**)&vproj, g_vproj);
    cudaGetSymbolAddress((void**)&sc,    g_sc);

    const float scale = 1.0f / 32.0f;   // 1/sqrt(1024)

    // 1. preprocess: q,k inputs split (hi+lo); v input + weights hi only
    {
        int n4 = MM * EE / 4;
        split_kernel<<<n4 / 256, 256>>>((const float4*)query, (ushort4*)qin_h, (ushort4*)qin_l, n4);
        split_kernel<<<n4 / 256, 256>>>((const float4*)key,   (ushort4*)kin_h, (ushort4*)kin_l, n4);
        conv_kernel<<<n4 / 256, 256>>>((const float4*)value,  (ushort4*)vin_h, n4);
        int w4 = EE * EE / 4;
        conv_kernel<<<w4 / 256, 256>>>((const float4*)QW, (ushort4*)wq_h, w4);
        conv_kernel<<<w4 / 256, 256>>>((const float4*)KW, (ushort4*)wk_h, w4);
        conv_kernel<<<w4 / 256, 256>>>((const float4*)VW, (ushort4*)wv_h, w4);
    }

    // 2. projections: q 2-pass -> split out; k 2-pass -> hi out; v 1-pass -> fp32
    {
        dim3 grid(EE / 128, MM / 128, 1);
        tc_gemm<1, true ><<<grid, 256, GEMM_SMEM>>>(qin_h, qin_l, wq_h, nullptr, q_h, q_l,
                                                    MM, EE, EE, 0, 0, 0, 1.0f);
        tc_gemm<2, true ><<<grid, 256, GEMM_SMEM>>>(kin_h, kin_l, wk_h, nullptr, k_h, nullptr,
                                                    MM, EE, EE, 0, 0, 0, 1.0f);
        tc_gemm<0, false><<<grid, 256, GEMM_SMEM>>>(vin_h, nullptr, wv_h, vproj, nullptr, nullptr,
                                                    MM, EE, EE, 0, 0, 0, 1.0f);
    }
    {
        dim3 grid(EE / 32, SS / 32, BB);
        tsplit_kernel<<<grid, dim3(32, 8)>>>(vproj, vt_h);
    }

    // 3. scores = (q @ k^T) * scale  (q split: 2-pass)
    {
        dim3 grid(SS / 128, SS / 128, BB);
        tc_gemm<0, true><<<grid, 256, GEMM_SMEM>>>(q_h, q_l, k_h, sc, nullptr, nullptr,
                                                   SS, SS, EE,
                                                   (long long)SS * EE, (long long)SS * EE,
                                                   (long long)SS * SS, scale);
    }

    // 4. softmax -> fp16 attn (hi only)
    softmax_split_kernel<<<BB * SS, 256>>>(sc, at_h);

    // 5. out = attn @ v  (1-pass)
    {
        dim3 grid(EE / 128, SS / 128, BB);
        tc_gemm<0, false><<<grid, 256, GEMM_SMEM>>>(at_h, nullptr, vt_h, out, nullptr, nullptr,
                                                    SS, EE, SS,
                                                    (long long)SS * SS, (long long)EE * SS,
                                                    (long long)SS * EE, 1.0f);
    }
}

// round 14
// speedup vs baseline: 1.4049x; 1.0851x over previous
#include <cuda_runtime.h>
#include <cuda_fp16.h>
#include <cstdint>

#define BB 4
#define SS 2048
#define EE 1024
#define MM (BB*SS)

// ---------------- PTX helpers (baseline ISA only; no sm_103a-accel features) ----------------
__device__ __forceinline__ uint32_t smem_u32(const void* p) {
    uint32_t a;
    asm("{ .reg .u64 t; cvta.to.shared.u64 t, %1; cvt.u32.u64 %0, t; }" : "=r"(a) : "l"(p));
    return a;
}

#define LDSM4(r0, r1, r2, r3, addr) \
    asm volatile("ldmatrix.sync.aligned.m8n8.x4.shared.b16 {%0,%1,%2,%3}, [%4];" \
        : "=r"(r0), "=r"(r1), "=r"(r2), "=r"(r3) : "r"(addr))

#define MMA16816(d, a, b0, b1) \
    asm volatile("mma.sync.aligned.m16n8k16.row.col.f32.f16.f16.f32 " \
        "{%0,%1,%2,%3}, {%4,%5,%6,%7}, {%8,%9}, {%0,%1,%2,%3};" \
        : "+f"((d)[0]), "+f"((d)[1]), "+f"((d)[2]), "+f"((d)[3]) \
        : "r"((a)[0]), "r"((a)[1]), "r"((a)[2]), "r"((a)[3]), "r"(b0), "r"(b1))

#define CP_ASYNC16(saddr, gptr) \
    asm volatile("cp.async.cg.shared.global [%0], [%1], 16;" :: "r"(saddr), "l"(gptr) : "memory")
#define CP_COMMIT() asm volatile("cp.async.commit_group;" ::: "memory")
#define CP_WAIT1()  asm volatile("cp.async.wait_group 1;" ::: "memory")

// ---------------- scratch (device globals, allocation-free) ----------------
__device__ __align__(1024) __half g_qin_hi[(size_t)MM * EE], g_qin_lo[(size_t)MM * EE];
__device__ __align__(1024) __half g_kin_hi[(size_t)MM * EE];
__device__ __align__(1024) __half g_vin_hi[(size_t)MM * EE];
__device__ __align__(1024) __half g_wq_hi[(size_t)EE * EE];
__device__ __align__(1024) __half g_wk_hi[(size_t)EE * EE];
__device__ __align__(1024) __half g_wv_hi[(size_t)EE * EE];
__device__ __align__(1024) __half g_q_hi[(size_t)MM * EE], g_q_lo[(size_t)MM * EE];
__device__ __align__(1024) __half g_k_hi[(size_t)MM * EE];
__device__ __align__(1024) float  g_vproj[(size_t)MM * EE];
__device__ __align__(1024) __half g_vt_hi[(size_t)MM * EE];
__device__ __align__(1024) float  g_sc[(size_t)BB * SS * SS];
__device__ __align__(1024) __half g_at_hi[(size_t)BB * SS * SS];

// ---------------- split / convert / transpose / softmax ----------------
__global__ void __launch_bounds__(256)
split_kernel(const float4* __restrict__ x, ushort4* __restrict__ hi, ushort4* __restrict__ lo, int n4)
{
    int i = blockIdx.x * blockDim.x + threadIdx.x;
    if (i >= n4) return;
    float4 v = x[i];
    __half hx = __float2half_rn(v.x), hy = __float2half_rn(v.y);
    __half hz = __float2half_rn(v.z), hw = __float2half_rn(v.w);
    ushort4 h, l;
    h.x = __half_as_ushort(hx); h.y = __half_as_ushort(hy);
    h.z = __half_as_ushort(hz); h.w = __half_as_ushort(hw);
    l.x = __half_as_ushort(__float2half_rn(v.x - __half2float(hx)));
    l.y = __half_as_ushort(__float2half_rn(v.y - __half2float(hy)));
    l.z = __half_as_ushort(__float2half_rn(v.z - __half2float(hz)));
    l.w = __half_as_ushort(__float2half_rn(v.w - __half2float(hw)));
    hi[i] = h; lo[i] = l;
}

__global__ void __launch_bounds__(256)
conv_kernel(const float4* __restrict__ x, ushort4* __restrict__ hi, int n4)
{
    int i = blockIdx.x * blockDim.x + threadIdx.x;
    if (i >= n4) return;
    float4 v = x[i];
    ushort4 h;
    h.x = __half_as_ushort(__float2half_rn(v.x));
    h.y = __half_as_ushort(__float2half_rn(v.y));
    h.z = __half_as_ushort(__float2half_rn(v.z));
    h.w = __half_as_ushort(__float2half_rn(v.w));
    hi[i] = h;
}

// transpose: v [BB][SS][EE] fp32 -> vt hi [BB][EE][SS] fp16
__global__ void __launch_bounds__(256)
tsplit_kernel(const float* __restrict__ v, __half* __restrict__ thi)
{
    __shared__ float tile[32][33];
    int b = blockIdx.z;
    int e0 = blockIdx.x * 32, s0 = blockIdx.y * 32;
    int tx = threadIdx.x, ty = threadIdx.y;  // 32 x 8
    #pragma unroll
    for (int k = 0; k < 32; k += 8)
        tile[ty + k][tx] = v[((long long)b * SS + s0 + ty + k) * EE + e0 + tx];
    __syncthreads();
    #pragma unroll
    for (int k = 0; k < 32; k += 8) {
        float val = tile[tx][ty + k];
        long long o = ((long long)b * EE + e0 + ty + k) * SS + s0 + tx;
        thi[o] = __float2half_rn(val);
    }
}

__global__ void __launch_bounds__(256)
softmax_split_kernel(const float* __restrict__ sc, __half* __restrict__ ahi)
{
    const float* p = sc + (long long)blockIdx.x * SS;
    long long obase = (long long)blockIdx.x * SS;
    const int t = threadIdx.x;
    __shared__ float red[8];

    float vals[SS / 256];
    float m = -1e30f;
    #pragma unroll
    for (int i = 0; i < SS / 256; i++) { vals[i] = p[t + i * 256]; m = fmaxf(m, vals[i]); }
    #pragma unroll
    for (int o = 16; o > 0; o >>= 1) m = fmaxf(m, __shfl_xor_sync(0xFFFFFFFFu, m, o));
    if ((t & 31) == 0) red[t >> 5] = m;
    __syncthreads();
    float mm = red[0];
    #pragma unroll
    for (int i = 1; i < 8; i++) mm = fmaxf(mm, red[i]);
    __syncthreads();

    float s = 0.0f;
    #pragma unroll
    for (int i = 0; i < SS / 256; i++) { vals[i] = __expf(vals[i] - mm); s += vals[i]; }
    #pragma unroll
    for (int o = 16; o > 0; o >>= 1) s += __shfl_xor_sync(0xFFFFFFFFu, s, o);
    if ((t & 31) == 0) red[t >> 5] = s;
    __syncthreads();
    float ssum = 0.0f;
    #pragma unroll
    for (int i = 0; i < 8; i++) ssum += red[i];
    float inv = 1.0f / ssum;

    #pragma unroll
    for (int i = 0; i < SS / 256; i++)
        ahi[obase + t + i * 256] = __float2half_rn(vals[i] * inv);
}

// ---------------- split-fp16 tensor-core GEMM ----------------
// SPLIT_A=true : C = alpha * (Ah+Al)[M,K] * Bh[N,K]^T  (2-pass MMA)
// SPLIT_A=false: C = alpha * Ah[M,K] * Bh[N,K]^T       (1-pass MMA)
// CTA tile 128x128, K-chunk 32, 8 warps (warp tile 32x64).
// 3-buffer / 2-ahead cp.async pipeline; 92KB smem/CTA -> 2 CTAs/SM.
static constexpr int TILE_A  = 128 * 80;               // 10240 B per 128-row tile
static constexpr int STAGE_B = 3 * TILE_A;             // 30720 B: Ah, Al, Bh
static constexpr int NSTAGE  = 3;
static constexpr int GEMM_SMEM = NSTAGE * STAGE_B;     // 92160

template <int OUT_MODE, bool SPLIT_A>   // OUT: 0 fp32 ; 1 split fp16 ; 2 fp16 hi
__global__ void __launch_bounds__(256, 2)
tc_gemm(const __half* __restrict__ Ahi, const __half* __restrict__ Alo,
        const __half* __restrict__ Bhi,
        float* __restrict__ Cf, __half* __restrict__ Chi, __half* __restrict__ Clo,
        int M, int N, int K, long long sA, long long sB, long long sC, float alpha)
{
    extern __shared__ char smem[];
    const uint32_t sbase = smem_u32(smem);
    const int tid = threadIdx.x;
    const int wid = tid >> 5;
    const int lid = tid & 31;
    const int wm = wid & 3;        // warp m block (32 rows)
    const int wn = wid >> 2;       // warp n block (64 cols)

    const int row0 = blockIdx.y * 128;
    const int col0 = blockIdx.x * 128;
    const long long zb = blockIdx.z;
    const __half* A0 = Ahi + zb * sA;
    const __half* A1 = SPLIT_A ? (Alo + zb * sA) : nullptr;
    const __half* B0 = Bhi + zb * sB;

    const int NK = K >> 5;  // K-chunks of 32

    auto load_stage = [&](int kc, int st) {
        const uint32_t stb = sbase + (uint32_t)st * STAGE_B;
        #pragma unroll
        for (int j = 0; j < 6; j++) {
            int i = tid + j * 256;      // 0..1535
            int tile = i >> 9;          // 0 Ah, 1 Al, 2 Bh
            if (!SPLIT_A && tile == 1) continue;
            int idx = i & 511;
            int row = idx >> 2, ch = idx & 3;
            const __half* src = (tile == 0) ? A0 : (tile == 1) ? A1 : B0;
            int base = (tile < 2) ? row0 : col0;
            const __half* g = src + (long long)(base + row) * K + kc * 32 + ch * 8;
            uint32_t s = stb + (uint32_t)(tile * TILE_A + row * 80 + ch * 16);
            CP_ASYNC16(s, __cvta_generic_to_global((const void*)g));
        }
        CP_COMMIT();
    };

    // 2-ahead preload into buffers 0,1
    load_stage(0, 0);
    load_stage(1, 1);

    float acc[2][8][4];
    #pragma unroll
    for (int a = 0; a < 2; a++)
        #pragma unroll
        for (int b = 0; b < 8; b++)
            #pragma unroll
            for (int c = 0; c < 4; c++) acc[a][b][c] = 0.0f;

    const int lrow = lid & 15;
    const int lch  = lid >> 4;

    for (int kc = 0; kc < NK; kc++) {
        CP_WAIT1();            // stage kc's group complete (<=1 pending)
        __syncthreads();       // also fences: all warps done reading stage kc-1's buffer

        const int st = kc % 3;
        const uint32_t stb = sbase + (uint32_t)st * STAGE_B;
        #pragma unroll
        for (int ks = 0; ks < 2; ks++) {
            const uint32_t choff = (uint32_t)((ks * 2 + lch) * 16);
            uint32_t ah[2][4], al[2][4];
            #pragma unroll
            for (int mf = 0; mf < 2; mf++) {
                uint32_t ra = stb + (uint32_t)((wm * 32 + mf * 16 + lrow) * 80) + choff;
                LDSM4(ah[mf][0], ah[mf][1], ah[mf][2], ah[mf][3], ra);
                if (SPLIT_A) LDSM4(al[mf][0], al[mf][1], al[mf][2], al[mf][3], ra + TILE_A);
            }
            uint32_t bh[4][4];
            #pragma unroll
            for (int nb = 0; nb < 4; nb++) {
                uint32_t rb = stb + (uint32_t)(2 * TILE_A + (wn * 64 + nb * 16 + lrow) * 80) + choff;
                LDSM4(bh[nb][0], bh[nb][1], bh[nb][2], bh[nb][3], rb);
            }
            #pragma unroll
            for (int nb = 0; nb < 4; nb++) {
                #pragma unroll
                for (int mf = 0; mf < 2; mf++) {
                    MMA16816(acc[mf][nb * 2 + 0], ah[mf], bh[nb][0], bh[nb][2]);
                    MMA16816(acc[mf][nb * 2 + 1], ah[mf], bh[nb][1], bh[nb][3]);
                }
            }
            if (SPLIT_A) {
                #pragma unroll
                for (int nb = 0; nb < 4; nb++) {
                    #pragma unroll
                    for (int mf = 0; mf < 2; mf++) {
                        MMA16816(acc[mf][nb * 2 + 0], al[mf], bh[nb][0], bh[nb][2]);
                        MMA16816(acc[mf][nb * 2 + 1], al[mf], bh[nb][1], bh[nb][3]);
                    }
                }
            }
        }
        // load kc+2 into buffer (kc+2)%3: consumed at kc-1, fenced by this
        // iteration's __syncthreads(). One commit per iter (empty at tail).
        if (kc + 2 < NK) load_stage(kc + 2, (kc + 2) % 3);
        else             CP_COMMIT();
    }

    // Epilogue
    const long long zC = zb * sC;
    const int tr = lid >> 2;
    const int tc = (lid & 3) * 2;
    #pragma unroll
    for (int mf = 0; mf < 2; mf++) {
        #pragma unroll
        for (int nf = 0; nf < 8; nf++) {
            int gn = col0 + wn * 64 + nf * 8 + tc;
            #pragma unroll
            for (int half = 0; half < 2; half++) {
                int gm = row0 + wm * 32 + mf * 16 + tr + half * 8;
                float v0 = acc[mf][nf][half * 2 + 0] * alpha;
                float v1 = acc[mf][nf][half * 2 + 1] * alpha;
                long long o = zC + (long long)gm * N + gn;
                if (OUT_MODE == 0) {
                    *reinterpret_cast<float2*>(&Cf[o]) = make_float2(v0, v1);
                } else if (OUT_MODE == 1) {
                    __half h0 = __float2half_rn(v0), h1 = __float2half_rn(v1);
                    __half l0 = __float2half_rn(v0 - __half2float(h0));
                    __half l1 = __float2half_rn(v1 - __half2float(h1));
                    *reinterpret_cast<__half2*>(&Chi[o]) = __halves2half2(h0, h1);
                    *reinterpret_cast<__half2*>(&Clo[o]) = __halves2half2(l0, l1);
                } else {
                    *reinterpret_cast<__half2*>(&Chi[o]) =
                        __halves2half2(__float2half_rn(v0), __float2half_rn(v1));
                }
            }
        }
    }
}

// ---------------- host ----------------
extern "C" void kernel_launch(void* const* d_in, const int* in_sizes, int n_in,
                              void* d_out, int out_size)
{
    const float* query = (const float*)d_in[0];
    const float* key   = (const float*)d_in[1];
    const float* value = (const float*)d_in[2];
    const float* QW    = (const float*)d_in[3];
    const float* KW    = (const float*)d_in[4];
    const float* VW    = (const float*)d_in[5];
    float* out = (float*)d_out;

    cudaFuncSetAttribute(tc_gemm<0, true>,  cudaFuncAttributeMaxDynamicSharedMemorySize, GEMM_SMEM);
    cudaFuncSetAttribute(tc_gemm<1, true>,  cudaFuncAttributeMaxDynamicSharedMemorySize, GEMM_SMEM);
    cudaFuncSetAttribute(tc_gemm<2, false>, cudaFuncAttributeMaxDynamicSharedMemorySize, GEMM_SMEM);
    cudaFuncSetAttribute(tc_gemm<0, false>, cudaFuncAttributeMaxDynamicSharedMemorySize, GEMM_SMEM);

    __half *qin_h, *qin_l, *kin_h, *vin_h;
    __half *wq_h, *wk_h, *wv_h;
    __half *q_h, *q_l, *k_h, *vt_h, *at_h;
    float *vproj, *sc;
    cudaGetSymbolAddress((void**)&qin_h, g_qin_hi); cudaGetSymbolAddress((void**)&qin_l, g_qin_lo);
    cudaGetSymbolAddress((void**)&kin_h, g_kin_hi);
    cudaGetSymbolAddress((void**)&vin_h, g_vin_hi);
    cudaGetSymbolAddress((void**)&wq_h,  g_wq_hi);
    cudaGetSymbolAddress((void**)&wk_h,  g_wk_hi);
    cudaGetSymbolAddress((void**)&wv_h,  g_wv_hi);
    cudaGetSymbolAddress((void**)&q_h,   g_q_hi);   cudaGetSymbolAddress((void**)&q_l,   g_q_lo);
    cudaGetSymbolAddress((void**)&k_h,   g_k_hi);
    cudaGetSymbolAddress((void**)&vt_h,  g_vt_hi);
    cudaGetSymbolAddress((void**)&at_h,  g_at_hi);
    cudaGetSymbolAddress((void**)&vproj, g_vproj);
    cudaGetSymbolAddress((void**)&sc,    g_sc);

    const float scale = 1.0f / 32.0f;   // 1/sqrt(1024)

    // 1. preprocess: q input split (hi+lo); k,v inputs + weights hi only
    {
        int n4 = MM * EE / 4;
        split_kernel<<<n4 / 256, 256>>>((const float4*)query, (ushort4*)qin_h, (ushort4*)qin_l, n4);
        conv_kernel<<<n4 / 256, 256>>>((const float4*)key,    (ushort4*)kin_h, n4);
        conv_kernel<<<n4 / 256, 256>>>((const float4*)value,  (ushort4*)vin_h, n4);
        int w4 = EE * EE / 4;
        conv_kernel<<<w4 / 256, 256>>>((const float4*)QW, (ushort4*)wq_h, w4);
        conv_kernel<<<w4 / 256, 256>>>((const float4*)KW, (ushort4*)wk_h, w4);
        conv_kernel<<<w4 / 256, 256>>>((const float4*)VW, (ushort4*)wv_h, w4);
    }

    // 2. projections: q 2-pass -> split out; k 1-pass -> hi out; v 1-pass -> fp32
    {
        dim3 grid(EE / 128, MM / 128, 1);
        tc_gemm<1, true ><<<grid, 256, GEMM_SMEM>>>(qin_h, qin_l, wq_h, nullptr, q_h, q_l,
                                                    MM, EE, EE, 0, 0, 0, 1.0f);
        tc_gemm<2, false><<<grid, 256, GEMM_SMEM>>>(kin_h, nullptr, wk_h, nullptr, k_h, nullptr,
                                                    MM, EE, EE, 0, 0, 0, 1.0f);
        tc_gemm<0, false><<<grid, 256, GEMM_SMEM>>>(vin_h, nullptr, wv_h, vproj, nullptr, nullptr,
                                                    MM, EE, EE, 0, 0, 0, 1.0f);
    }
    {
        dim3 grid(EE / 32, SS / 32, BB);
        tsplit_kernel<<<grid, dim3(32, 8)>>>(vproj, vt_h);
    }

    // 3. scores = (q @ k^T) * scale  (q split: 2-pass)
    {
        dim3 grid(SS / 128, SS / 128, BB);
        tc_gemm<0, true><<<grid, 256, GEMM_SMEM>>>(q_h, q_l, k_h, sc, nullptr, nullptr,
                                                   SS, SS, EE,
                                                   (long long)SS * EE, (long long)SS * EE,
                                                   (long long)SS * SS, scale);
    }

    // 4. softmax -> fp16 attn (hi only)
    softmax_split_kernel<<<BB * SS, 256>>>(sc, at_h);

    // 5. out = attn @ v  (1-pass)
    {
        dim3 grid(EE / 128, SS / 128, BB);
        tc_gemm<0, false><<<grid, 256, GEMM_SMEM>>>(at_h, nullptr, vt_h, out, nullptr, nullptr,
                                                    SS, EE, SS,
                                                    (long long)SS * SS, (long long)EE * SS,
                                                    (long long)SS * EE, 1.0f);
    }
}

// round 15
// speedup vs baseline: 1.5205x; 1.0823x over previous
#include <cuda_runtime.h>
#include <cuda_fp16.h>
#include <cstdint>

#define BB 4
#define SS 2048
#define EE 1024
#define MM (BB*SS)

// ---------------- PTX helpers (baseline ISA only; no sm_103a-accel features) ----------------
__device__ __forceinline__ uint32_t smem_u32(const void* p) {
    uint32_t a;
    asm("{ .reg .u64 t; cvta.to.shared.u64 t, %1; cvt.u32.u64 %0, t; }" : "=r"(a) : "l"(p));
    return a;
}

#define LDSM4(r0, r1, r2, r3, addr) \
    asm volatile("ldmatrix.sync.aligned.m8n8.x4.shared.b16 {%0,%1,%2,%3}, [%4];" \
        : "=r"(r0), "=r"(r1), "=r"(r2), "=r"(r3) : "r"(addr))

#define MMA16816(d, a, b0, b1) \
    asm volatile("mma.sync.aligned.m16n8k16.row.col.f32.f16.f16.f32 " \
        "{%0,%1,%2,%3}, {%4,%5,%6,%7}, {%8,%9}, {%0,%1,%2,%3};" \
        : "+f"((d)[0]), "+f"((d)[1]), "+f"((d)[2]), "+f"((d)[3]) \
        : "r"((a)[0]), "r"((a)[1]), "r"((a)[2]), "r"((a)[3]), "r"(b0), "r"(b1))

#define CP_ASYNC16(saddr, gptr) \
    asm volatile("cp.async.cg.shared.global [%0], [%1], 16;" :: "r"(saddr), "l"(gptr) : "memory")
#define CP_COMMIT() asm volatile("cp.async.commit_group;" ::: "memory")
#define CP_WAIT1()  asm volatile("cp.async.wait_group 1;" ::: "memory")

// ---------------- scratch (device globals, allocation-free) ----------------
__device__ __align__(1024) __half g_qin_hi[(size_t)MM * EE];
__device__ __align__(1024) __half g_kin_hi[(size_t)MM * EE];
__device__ __align__(1024) __half g_vin_hi[(size_t)MM * EE];
__device__ __align__(1024) __half g_wq_hi[(size_t)EE * EE];
__device__ __align__(1024) __half g_wk_hi[(size_t)EE * EE];
__device__ __align__(1024) __half g_wv_hi[(size_t)EE * EE];
__device__ __align__(1024) __half g_q_hi[(size_t)MM * EE], g_q_lo[(size_t)MM * EE];
__device__ __align__(1024) __half g_k_hi[(size_t)MM * EE];
__device__ __align__(1024) float  g_vproj[(size_t)MM * EE];
__device__ __align__(1024) __half g_vt_hi[(size_t)MM * EE];
__device__ __align__(1024) float  g_sc[(size_t)BB * SS * SS];
__device__ __align__(1024) __half g_at_hi[(size_t)BB * SS * SS];

// ---------------- convert / transpose / softmax ----------------
__global__ void __launch_bounds__(256)
conv_kernel(const float4* __restrict__ x, ushort4* __restrict__ hi, int n4)
{
    int i = blockIdx.x * blockDim.x + threadIdx.x;
    if (i >= n4) return;
    float4 v = x[i];
    ushort4 h;
    h.x = __half_as_ushort(__float2half_rn(v.x));
    h.y = __half_as_ushort(__float2half_rn(v.y));
    h.z = __half_as_ushort(__float2half_rn(v.z));
    h.w = __half_as_ushort(__float2half_rn(v.w));
    hi[i] = h;
}

// transpose: v [BB][SS][EE] fp32 -> vt hi [BB][EE][SS] fp16
__global__ void __launch_bounds__(256)
tsplit_kernel(const float* __restrict__ v, __half* __restrict__ thi)
{
    __shared__ float tile[32][33];
    int b = blockIdx.z;
    int e0 = blockIdx.x * 32, s0 = blockIdx.y * 32;
    int tx = threadIdx.x, ty = threadIdx.y;  // 32 x 8
    #pragma unroll
    for (int k = 0; k < 32; k += 8)
        tile[ty + k][tx] = v[((long long)b * SS + s0 + ty + k) * EE + e0 + tx];
    __syncthreads();
    #pragma unroll
    for (int k = 0; k < 32; k += 8) {
        float val = tile[tx][ty + k];
        long long o = ((long long)b * EE + e0 + ty + k) * SS + s0 + tx;
        thi[o] = __float2half_rn(val);
    }
}

__global__ void __launch_bounds__(256)
softmax_split_kernel(const float* __restrict__ sc, __half* __restrict__ ahi)
{
    const float* p = sc + (long long)blockIdx.x * SS;
    long long obase = (long long)blockIdx.x * SS;
    const int t = threadIdx.x;
    __shared__ float red[8];

    float vals[SS / 256];
    float m = -1e30f;
    #pragma unroll
    for (int i = 0; i < SS / 256; i++) { vals[i] = p[t + i * 256]; m = fmaxf(m, vals[i]); }
    #pragma unroll
    for (int o = 16; o > 0; o >>= 1) m = fmaxf(m, __shfl_xor_sync(0xFFFFFFFFu, m, o));
    if ((t & 31) == 0) red[t >> 5] = m;
    __syncthreads();
    float mm = red[0];
    #pragma unroll
    for (int i = 1; i < 8; i++) mm = fmaxf(mm, red[i]);
    __syncthreads();

    float s = 0.0f;
    #pragma unroll
    for (int i = 0; i < SS / 256; i++) { vals[i] = __expf(vals[i] - mm); s += vals[i]; }
    #pragma unroll
    for (int o = 16; o > 0; o >>= 1) s += __shfl_xor_sync(0xFFFFFFFFu, s, o);
    if ((t & 31) == 0) red[t >> 5] = s;
    __syncthreads();
    float ssum = 0.0f;
    #pragma unroll
    for (int i = 0; i < 8; i++) ssum += red[i];
    float inv = 1.0f / ssum;

    #pragma unroll
    for (int i = 0; i < SS / 256; i++)
        ahi[obase + t + i * 256] = __float2half_rn(vals[i] * inv);
}

// ---------------- split-fp16 tensor-core GEMM ----------------
// SPLIT_A=true : C = alpha * (Ah+Al)[M,K] * Bh[N,K]^T  (2-pass MMA)
// SPLIT_A=false: C = alpha * Ah[M,K] * Bh[N,K]^T       (1-pass MMA)
// CTA tile 128x128, K-chunk 32, 8 warps (warp tile 32x64).
// 3-buffer / 2-ahead cp.async pipeline; 92KB smem/CTA -> 2 CTAs/SM.
static constexpr int TILE_A  = 128 * 80;               // 10240 B per 128-row tile
static constexpr int STAGE_B = 3 * TILE_A;             // 30720 B: Ah, Al, Bh
static constexpr int NSTAGE  = 3;
static constexpr int GEMM_SMEM = NSTAGE * STAGE_B;     // 92160

template <int OUT_MODE, bool SPLIT_A>   // OUT: 0 fp32 ; 1 split fp16 ; 2 fp16 hi
__global__ void __launch_bounds__(256, 2)
tc_gemm(const __half* __restrict__ Ahi, const __half* __restrict__ Alo,
        const __half* __restrict__ Bhi,
        float* __restrict__ Cf, __half* __restrict__ Chi, __half* __restrict__ Clo,
        int M, int N, int K, long long sA, long long sB, long long sC, float alpha)
{
    extern __shared__ char smem[];
    const uint32_t sbase = smem_u32(smem);
    const int tid = threadIdx.x;
    const int wid = tid >> 5;
    const int lid = tid & 31;
    const int wm = wid & 3;        // warp m block (32 rows)
    const int wn = wid >> 2;       // warp n block (64 cols)

    const int row0 = blockIdx.y * 128;
    const int col0 = blockIdx.x * 128;
    const long long zb = blockIdx.z;
    const __half* A0 = Ahi + zb * sA;
    const __half* A1 = SPLIT_A ? (Alo + zb * sA) : nullptr;
    const __half* B0 = Bhi + zb * sB;

    const int NK = K >> 5;  // K-chunks of 32

    auto load_stage = [&](int kc, int st) {
        const uint32_t stb = sbase + (uint32_t)st * STAGE_B;
        #pragma unroll
        for (int j = 0; j < 6; j++) {
            int i = tid + j * 256;      // 0..1535
            int tile = i >> 9;          // 0 Ah, 1 Al, 2 Bh
            if (!SPLIT_A && tile == 1) continue;
            int idx = i & 511;
            int row = idx >> 2, ch = idx & 3;
            const __half* src = (tile == 0) ? A0 : (tile == 1) ? A1 : B0;
            int base = (tile < 2) ? row0 : col0;
            const __half* g = src + (long long)(base + row) * K + kc * 32 + ch * 8;
            uint32_t s = stb + (uint32_t)(tile * TILE_A + row * 80 + ch * 16);
            CP_ASYNC16(s, __cvta_generic_to_global((const void*)g));
        }
        CP_COMMIT();
    };

    // 2-ahead preload into buffers 0,1
    load_stage(0, 0);
    load_stage(1, 1);

    float acc[2][8][4];
    #pragma unroll
    for (int a = 0; a < 2; a++)
        #pragma unroll
        for (int b = 0; b < 8; b++)
            #pragma unroll
            for (int c = 0; c < 4; c++) acc[a][b][c] = 0.0f;

    const int lrow = lid & 15;
    const int lch  = lid >> 4;

    for (int kc = 0; kc < NK; kc++) {
        CP_WAIT1();            // stage kc's group complete (<=1 pending)
        __syncthreads();       // also fences: all warps done reading stage kc-1's buffer

        const int st = kc % 3;
        const uint32_t stb = sbase + (uint32_t)st * STAGE_B;
        #pragma unroll
        for (int ks = 0; ks < 2; ks++) {
            const uint32_t choff = (uint32_t)((ks * 2 + lch) * 16);
            uint32_t ah[2][4], al[2][4];
            #pragma unroll
            for (int mf = 0; mf < 2; mf++) {
                uint32_t ra = stb + (uint32_t)((wm * 32 + mf * 16 + lrow) * 80) + choff;
                LDSM4(ah[mf][0], ah[mf][1], ah[mf][2], ah[mf][3], ra);
                if (SPLIT_A) LDSM4(al[mf][0], al[mf][1], al[mf][2], al[mf][3], ra + TILE_A);
            }
            uint32_t bh[4][4];
            #pragma unroll
            for (int nb = 0; nb < 4; nb++) {
                uint32_t rb = stb + (uint32_t)(2 * TILE_A + (wn * 64 + nb * 16 + lrow) * 80) + choff;
                LDSM4(bh[nb][0], bh[nb][1], bh[nb][2], bh[nb][3], rb);
            }
            #pragma unroll
            for (int nb = 0; nb < 4; nb++) {
                #pragma unroll
                for (int mf = 0; mf < 2; mf++) {
                    MMA16816(acc[mf][nb * 2 + 0], ah[mf], bh[nb][0], bh[nb][2]);
                    MMA16816(acc[mf][nb * 2 + 1], ah[mf], bh[nb][1], bh[nb][3]);
                }
            }
            if (SPLIT_A) {
                #pragma unroll
                for (int nb = 0; nb < 4; nb++) {
                    #pragma unroll
                    for (int mf = 0; mf < 2; mf++) {
                        MMA16816(acc[mf][nb * 2 + 0], al[mf], bh[nb][0], bh[nb][2]);
                        MMA16816(acc[mf][nb * 2 + 1], al[mf], bh[nb][1], bh[nb][3]);
                    }
                }
            }
        }
        // load kc+2 into buffer (kc+2)%3: consumed at kc-1, fenced by this
        // iteration's __syncthreads(). One commit per iter (empty at tail).
        if (kc + 2 < NK) load_stage(kc + 2, (kc + 2) % 3);
        else             CP_COMMIT();
    }

    // Epilogue
    const long long zC = zb * sC;
    const int tr = lid >> 2;
    const int tc = (lid & 3) * 2;
    #pragma unroll
    for (int mf = 0; mf < 2; mf++) {
        #pragma unroll
        for (int nf = 0; nf < 8; nf++) {
            int gn = col0 + wn * 64 + nf * 8 + tc;
            #pragma unroll
            for (int half = 0; half < 2; half++) {
                int gm = row0 + wm * 32 + mf * 16 + tr + half * 8;
                float v0 = acc[mf][nf][half * 2 + 0] * alpha;
                float v1 = acc[mf][nf][half * 2 + 1] * alpha;
                long long o = zC + (long long)gm * N + gn;
                if (OUT_MODE == 0) {
                    *reinterpret_cast<float2*>(&Cf[o]) = make_float2(v0, v1);
                } else if (OUT_MODE == 1) {
                    __half h0 = __float2half_rn(v0), h1 = __float2half_rn(v1);
                    __half l0 = __float2half_rn(v0 - __half2float(h0));
                    __half l1 = __float2half_rn(v1 - __half2float(h1));
                    *reinterpret_cast<__half2*>(&Chi[o]) = __halves2half2(h0, h1);
                    *reinterpret_cast<__half2*>(&Clo[o]) = __halves2half2(l0, l1);
                } else {
                    *reinterpret_cast<__half2*>(&Chi[o]) =
                        __halves2half2(__float2half_rn(v0), __float2half_rn(v1));
                }
            }
        }
    }
}

// ---------------- host ----------------
extern "C" void kernel_launch(void* const* d_in, const int* in_sizes, int n_in,
                              void* d_out, int out_size)
{
    const float* query = (const float*)d_in[0];
    const float* key   = (const float*)d_in[1];
    const float* value = (const float*)d_in[2];
    const float* QW    = (const float*)d_in[3];
    const float* KW    = (const float*)d_in[4];
    const float* VW    = (const float*)d_in[5];
    float* out = (float*)d_out;

    cudaFuncSetAttribute(tc_gemm<0, true>,  cudaFuncAttributeMaxDynamicSharedMemorySize, GEMM_SMEM);
    cudaFuncSetAttribute(tc_gemm<1, false>, cudaFuncAttributeMaxDynamicSharedMemorySize, GEMM_SMEM);
    cudaFuncSetAttribute(tc_gemm<2, false>, cudaFuncAttributeMaxDynamicSharedMemorySize, GEMM_SMEM);
    cudaFuncSetAttribute(tc_gemm<0, false>, cudaFuncAttributeMaxDynamicSharedMemorySize, GEMM_SMEM);

    __half *qin_h, *kin_h, *vin_h;
    __half *wq_h, *wk_h, *wv_h;
    __half *q_h, *q_l, *k_h, *vt_h, *at_h;
    float *vproj, *sc;
    cudaGetSymbolAddress((void**)&qin_h, g_qin_hi);
    cudaGetSymbolAddress((void**)&kin_h, g_kin_hi);
    cudaGetSymbolAddress((void**)&vin_h, g_vin_hi);
    cudaGetSymbolAddress((void**)&wq_h,  g_wq_hi);
    cudaGetSymbolAddress((void**)&wk_h,  g_wk_hi);
    cudaGetSymbolAddress((void**)&wv_h,  g_wv_hi);
    cudaGetSymbolAddress((void**)&q_h,   g_q_hi);   cudaGetSymbolAddress((void**)&q_l,   g_q_lo);
    cudaGetSymbolAddress((void**)&k_h,   g_k_hi);
    cudaGetSymbolAddress((void**)&vt_h,  g_vt_hi);
    cudaGetSymbolAddress((void**)&at_h,  g_at_hi);
    cudaGetSymbolAddress((void**)&vproj, g_vproj);
    cudaGetSymbolAddress((void**)&sc,    g_sc);

    const float scale = 1.0f / 32.0f;   // 1/sqrt(1024)

    // 1. preprocess: all inputs + weights -> fp16 hi only
    {
        int n4 = MM * EE / 4;
        conv_kernel<<<n4 / 256, 256>>>((const float4*)query,  (ushort4*)qin_h, n4);
        conv_kernel<<<n4 / 256, 256>>>((const float4*)key,    (ushort4*)kin_h, n4);
        conv_kernel<<<n4 / 256, 256>>>((const float4*)value,  (ushort4*)vin_h, n4);
        int w4 = EE * EE / 4;
        conv_kernel<<<w4 / 256, 256>>>((const float4*)QW, (ushort4*)wq_h, w4);
        conv_kernel<<<w4 / 256, 256>>>((const float4*)KW, (ushort4*)wk_h, w4);
        conv_kernel<<<w4 / 256, 256>>>((const float4*)VW, (ushort4*)wv_h, w4);
    }

    // 2. projections: q 1-pass -> split out (fp32 acc preserved as hi+lo);
    //    k 1-pass -> hi out; v 1-pass -> fp32
    {
        dim3 grid(EE / 128, MM / 128, 1);
        tc_gemm<1, false><<<grid, 256, GEMM_SMEM>>>(qin_h, nullptr, wq_h, nullptr, q_h, q_l,
                                                    MM, EE, EE, 0, 0, 0, 1.0f);
        tc_gemm<2, false><<<grid, 256, GEMM_SMEM>>>(kin_h, nullptr, wk_h, nullptr, k_h, nullptr,
                                                    MM, EE, EE, 0, 0, 0, 1.0f);
        tc_gemm<0, false><<<grid, 256, GEMM_SMEM>>>(vin_h, nullptr, wv_h, vproj, nullptr, nullptr,
                                                    MM, EE, EE, 0, 0, 0, 1.0f);
    }
    {
        dim3 grid(EE / 32, SS / 32, BB);
        tsplit_kernel<<<grid, dim3(32, 8)>>>(vproj, vt_h);
    }

    // 3. scores = (q @ k^T) * scale  (q split: 2-pass -- load-bearing precision)
    {
        dim3 grid(SS / 128, SS / 128, BB);
        tc_gemm<0, true><<<grid, 256, GEMM_SMEM>>>(q_h, q_l, k_h, sc, nullptr, nullptr,
                                                   SS, SS, EE,
                                                   (long long)SS * EE, (long long)SS * EE,
                                                   (long long)SS * SS, scale);
    }

    // 4. softmax -> fp16 attn (hi only)
    softmax_split_kernel<<<BB * SS, 256>>>(sc, at_h);

    // 5. out = attn @ v  (1-pass)
    {
        dim3 grid(EE / 128, SS / 128, BB);
        tc_gemm<0, false><<<grid, 256, GEMM_SMEM>>>(at_h, nullptr, vt_h, out, nullptr, nullptr,
                                                    SS, EE, SS,
                                                    (long long)SS * SS, (long long)EE * SS,
                                                    (long long)SS * EE, 1.0f);
    }
}

// round 17
// speedup vs baseline: 1.8484x; 1.2157x over previous
#include <cuda_runtime.h>
#include <cuda_fp16.h>
#include <cstdint>

#define BB 4
#define SS 2048
#define EE 1024
#define MM (BB*SS)

// ---------------- PTX helpers (baseline ISA only; no sm_103a-accel features) ----------------
__device__ __forceinline__ uint32_t smem_u32(const void* p) {
    uint32_t a;
    asm("{ .reg .u64 t; cvta.to.shared.u64 t, %1; cvt.u32.u64 %0, t; }" : "=r"(a) : "l"(p));
    return a;
}

#define LDSM4(r0, r1, r2, r3, addr) \
    asm volatile("ldmatrix.sync.aligned.m8n8.x4.shared.b16 {%0,%1,%2,%3}, [%4];" \
        : "=r"(r0), "=r"(r1), "=r"(r2), "=r"(r3) : "r"(addr))

#define MMA16816(d, a, b0, b1) \
    asm volatile("mma.sync.aligned.m16n8k16.row.col.f32.f16.f16.f32 " \
        "{%0,%1,%2,%3}, {%4,%5,%6,%7}, {%8,%9}, {%0,%1,%2,%3};" \
        : "+f"((d)[0]), "+f"((d)[1]), "+f"((d)[2]), "+f"((d)[3]) \
        : "r"((a)[0]), "r"((a)[1]), "r"((a)[2]), "r"((a)[3]), "r"(b0), "r"(b1))

#define CP_ASYNC16(saddr, gptr) \
    asm volatile("cp.async.cg.shared.global [%0], [%1], 16;" :: "r"(saddr), "l"(gptr) : "memory")
#define CP_COMMIT() asm volatile("cp.async.commit_group;" ::: "memory")
#define CP_WAIT1()  asm volatile("cp.async.wait_group 1;" ::: "memory")

// ---------------- scratch (device globals, allocation-free) ----------------
__device__ __align__(1024) __half g_qin_hi[(size_t)MM * EE];
__device__ __align__(1024) __half g_kin_hi[(size_t)MM * EE];
__device__ __align__(1024) __half g_vin_hi[(size_t)MM * EE];
__device__ __align__(1024) __half g_wq_hi[(size_t)EE * EE];
__device__ __align__(1024) __half g_wk_hi[(size_t)EE * EE];
__device__ __align__(1024) __half g_wv_hi[(size_t)EE * EE];
__device__ __align__(1024) __half g_q_hi[(size_t)MM * EE];
__device__ __align__(1024) __half g_k_hi[(size_t)MM * EE];
__device__ __align__(1024) __half g_vt_hi[(size_t)MM * EE];
__device__ __align__(1024) float  g_sc[(size_t)BB * SS * SS];
__device__ __align__(1024) __half g_at_hi[(size_t)BB * SS * SS];

// ---------------- fused convert (3 tensors per launch) ----------------
__global__ void __launch_bounds__(256)
conv3_kernel(const float4* __restrict__ x0, const float4* __restrict__ x1,
             const float4* __restrict__ x2,
             ushort4* __restrict__ h0, ushort4* __restrict__ h1,
             ushort4* __restrict__ h2, int n4)
{
    int i = blockIdx.x * blockDim.x + threadIdx.x;
    if (i >= n4) return;
    const float4* x = (blockIdx.y == 0) ? x0 : (blockIdx.y == 1) ? x1 : x2;
    ushort4*      o = (blockIdx.y == 0) ? h0 : (blockIdx.y == 1) ? h1 : h2;
    float4 v = x[i];
    ushort4 h;
    h.x = __half_as_ushort(__float2half_rn(v.x));
    h.y = __half_as_ushort(__float2half_rn(v.y));
    h.z = __half_as_ushort(__float2half_rn(v.z));
    h.w = __half_as_ushort(__float2half_rn(v.w));
    o[i] = h;
}

__global__ void __launch_bounds__(256)
softmax_split_kernel(const float* __restrict__ sc, __half* __restrict__ ahi)
{
    const float* p = sc + (long long)blockIdx.x * SS;
    long long obase = (long long)blockIdx.x * SS;
    const int t = threadIdx.x;
    __shared__ float red[8];

    float vals[SS / 256];
    float m = -1e30f;
    #pragma unroll
    for (int i = 0; i < SS / 256; i++) { vals[i] = p[t + i * 256]; m = fmaxf(m, vals[i]); }
    #pragma unroll
    for (int o = 16; o > 0; o >>= 1) m = fmaxf(m, __shfl_xor_sync(0xFFFFFFFFu, m, o));
    if ((t & 31) == 0) red[t >> 5] = m;
    __syncthreads();
    float mm = red[0];
    #pragma unroll
    for (int i = 1; i < 8; i++) mm = fmaxf(mm, red[i]);
    __syncthreads();

    float s = 0.0f;
    #pragma unroll
    for (int i = 0; i < SS / 256; i++) { vals[i] = __expf(vals[i] - mm); s += vals[i]; }
    #pragma unroll
    for (int o = 16; o > 0; o >>= 1) s += __shfl_xor_sync(0xFFFFFFFFu, s, o);
    if ((t & 31) == 0) red[t >> 5] = s;
    __syncthreads();
    float ssum = 0.0f;
    #pragma unroll
    for (int i = 0; i < 8; i++) ssum += red[i];
    float inv = 1.0f / ssum;

    #pragma unroll
    for (int i = 0; i < SS / 256; i++)
        ahi[obase + t + i * 256] = __float2half_rn(vals[i] * inv);
}

// ---------------- fp16 tensor-core GEMM ----------------
// C = alpha * Ah[M,K] * Bh[N,K]^T   (both K-major), fp32 accumulate.
// CTA tile 128x128, K-chunk 32, 8 warps (warp tile 32x64).
// 3-buffer / 2-ahead cp.async pipeline; 62KB smem/CTA -> 2 CTAs/SM.
static constexpr int TILE_A  = 128 * 80;               // 10240 B per 128-row tile
static constexpr int STAGE_B = 2 * TILE_A;             // 20480 B: Ah, Bh
static constexpr int NSTAGE  = 3;
static constexpr int GEMM_SMEM = NSTAGE * STAGE_B;     // 61440

template <int OUT_MODE>   // OUT: 0 fp32 ; 2 fp16 hi
__global__ void __launch_bounds__(256, 2)
tc_gemm(const __half* __restrict__ Ahi, const __half* __restrict__ Bhi,
        float* __restrict__ Cf, __half* __restrict__ Chi,
        int M, int N, int K, long long sA, long long sB, long long sC, float alpha)
{
    extern __shared__ char smem[];
    const uint32_t sbase = smem_u32(smem);
    const int tid = threadIdx.x;
    const int wid = tid >> 5;
    const int lid = tid & 31;
    const int wm = wid & 3;        // warp m block (32 rows)
    const int wn = wid >> 2;       // warp n block (64 cols)

    const int row0 = blockIdx.y * 128;
    const int col0 = blockIdx.x * 128;
    const long long zb = blockIdx.z;
    const __half* A0 = Ahi + zb * sA;
    const __half* B0 = Bhi + zb * sB;

    const int NK = K >> 5;  // K-chunks of 32

    auto load_stage = [&](int kc, int st) {
        const uint32_t stb = sbase + (uint32_t)st * STAGE_B;
        #pragma unroll
        for (int j = 0; j < 4; j++) {
            int i = tid + j * 256;      // 0..1023
            int tile = i >> 9;          // 0 Ah, 1 Bh
            int idx = i & 511;
            int row = idx >> 2, ch = idx & 3;
            const __half* src = (tile == 0) ? A0 : B0;
            int base = (tile == 0) ? row0 : col0;
            const __half* g = src + (long long)(base + row) * K + kc * 32 + ch * 8;
            uint32_t s = stb + (uint32_t)(tile * TILE_A + row * 80 + ch * 16);
            CP_ASYNC16(s, __cvta_generic_to_global((const void*)g));
        }
        CP_COMMIT();
    };

    // 2-ahead preload into buffers 0,1
    load_stage(0, 0);
    load_stage(1, 1);

    float acc[2][8][4];
    #pragma unroll
    for (int a = 0; a < 2; a++)
        #pragma unroll
        for (int b = 0; b < 8; b++)
            #pragma unroll
            for (int c = 0; c < 4; c++) acc[a][b][c] = 0.0f;

    const int lrow = lid & 15;
    const int lch  = lid >> 4;

    for (int kc = 0; kc < NK; kc++) {
        CP_WAIT1();            // stage kc's group complete (<=1 pending)
        __syncthreads();       // fences: all warps done reading stage kc-1's buffer

        const int st = kc % 3;
        const uint32_t stb = sbase + (uint32_t)st * STAGE_B;
        #pragma unroll
        for (int ks = 0; ks < 2; ks++) {
            const uint32_t choff = (uint32_t)((ks * 2 + lch) * 16);
            uint32_t ah[2][4];
            #pragma unroll
            for (int mf = 0; mf < 2; mf++) {
                uint32_t ra = stb + (uint32_t)((wm * 32 + mf * 16 + lrow) * 80) + choff;
                LDSM4(ah[mf][0], ah[mf][1], ah[mf][2], ah[mf][3], ra);
            }
            uint32_t bh[4][4];
            #pragma unroll
            for (int nb = 0; nb < 4; nb++) {
                uint32_t rb = stb + (uint32_t)(TILE_A + (wn * 64 + nb * 16 + lrow) * 80) + choff;
                LDSM4(bh[nb][0], bh[nb][1], bh[nb][2], bh[nb][3], rb);
            }
            #pragma unroll
            for (int nb = 0; nb < 4; nb++) {
                #pragma unroll
                for (int mf = 0; mf < 2; mf++) {
                    MMA16816(acc[mf][nb * 2 + 0], ah[mf], bh[nb][0], bh[nb][2]);
                    MMA16816(acc[mf][nb * 2 + 1], ah[mf], bh[nb][1], bh[nb][3]);
                }
            }
        }
        // load kc+2 into buffer (kc+2)%3: consumed at kc-1, fenced by this
        // iteration's __syncthreads(). One commit per iter (empty at tail).
        if (kc + 2 < NK) load_stage(kc + 2, (kc + 2) % 3);
        else             CP_COMMIT();
    }

    // Epilogue
    const long long zC = zb * sC;
    const int tr = lid >> 2;
    const int tc = (lid & 3) * 2;
    #pragma unroll
    for (int mf = 0; mf < 2; mf++) {
        #pragma unroll
        for (int nf = 0; nf < 8; nf++) {
            int gn = col0 + wn * 64 + nf * 8 + tc;
            #pragma unroll
            for (int half = 0; half < 2; half++) {
                int gm = row0 + wm * 32 + mf * 16 + tr + half * 8;
                float v0 = acc[mf][nf][half * 2 + 0] * alpha;
                float v1 = acc[mf][nf][half * 2 + 1] * alpha;
                long long o = zC + (long long)gm * N + gn;
                if (OUT_MODE == 0) {
                    *reinterpret_cast<float2*>(&Cf[o]) = make_float2(v0, v1);
                } else {
                    *reinterpret_cast<__half2*>(&Chi[o]) =
                        __halves2half2(__float2half_rn(v0), __float2half_rn(v1));
                }
            }
        }
    }
}

// ---------------- host ----------------
extern "C" void kernel_launch(void* const* d_in, const int* in_sizes, int n_in,
                              void* d_out, int out_size)
{
    const float* query = (const float*)d_in[0];
    const float* key   = (const float*)d_in[1];
    const float* value = (const float*)d_in[2];
    const float* QW    = (const float*)d_in[3];
    const float* KW    = (const float*)d_in[4];
    const float* VW    = (const float*)d_in[5];
    float* out = (float*)d_out;

    cudaFuncSetAttribute(tc_gemm<0>, cudaFuncAttributeMaxDynamicSharedMemorySize, GEMM_SMEM);
    cudaFuncSetAttribute(tc_gemm<2>, cudaFuncAttributeMaxDynamicSharedMemorySize, GEMM_SMEM);

    __half *qin_h, *kin_h, *vin_h;
    __half *wq_h, *wk_h, *wv_h;
    __half *q_h, *k_h, *vt_h, *at_h;
    float *sc;
    cudaGetSymbolAddress((void**)&qin_h, g_qin_hi);
    cudaGetSymbolAddress((void**)&kin_h, g_kin_hi);
    cudaGetSymbolAddress((void**)&vin_h, g_vin_hi);
    cudaGetSymbolAddress((void**)&wq_h,  g_wq_hi);
    cudaGetSymbolAddress((void**)&wk_h,  g_wk_hi);
    cudaGetSymbolAddress((void**)&wv_h,  g_wv_hi);
    cudaGetSymbolAddress((void**)&q_h,   g_q_hi);
    cudaGetSymbolAddress((void**)&k_h,   g_k_hi);
    cudaGetSymbolAddress((void**)&vt_h,  g_vt_hi);
    cudaGetSymbolAddress((void**)&at_h,  g_at_hi);
    cudaGetSymbolAddress((void**)&sc,    g_sc);

    const float scale = 1.0f / 32.0f;   // 1/sqrt(1024)

    // 1. preprocess: inputs + weights -> fp16 (two fused launches)
    {
        int n4 = MM * EE / 4;
        dim3 gi(n4 / 256, 3);
        conv3_kernel<<<gi, 256>>>((const float4*)query, (const float4*)key, (const float4*)value,
                                  (ushort4*)qin_h, (ushort4*)kin_h, (ushort4*)vin_h, n4);
        int w4 = EE * EE / 4;
        dim3 gw(w4 / 256, 3);
        conv3_kernel<<<gw, 256>>>((const float4*)QW, (const float4*)KW, (const float4*)VW,
                                  (ushort4*)wq_h, (ushort4*)wk_h, (ushort4*)wv_h, w4);
    }

    // 2. projections (all 1-pass fp16 out):
    //    q, k: [MM,EE] = in @ W^T
    //    vt:   [EE,SS] per batch = Wv @ vin^T  (direct transposed output;
    //          fp32-acc -> fp16 rounding identical to old vproj+tsplit path)
    {
        dim3 grid(EE / 128, MM / 128, 1);
        tc_gemm<2><<<grid, 256, GEMM_SMEM>>>(qin_h, wq_h, nullptr, q_h,
                                             MM, EE, EE, 0, 0, 0, 1.0f);
        tc_gemm<2><<<grid, 256, GEMM_SMEM>>>(kin_h, wk_h, nullptr, k_h,
                                             MM, EE, EE, 0, 0, 0, 1.0f);
    }
    {
        dim3 grid(SS / 128, EE / 128, BB);
        tc_gemm<2><<<grid, 256, GEMM_SMEM>>>(wv_h, vin_h, nullptr, vt_h,
                                             EE, SS, EE,
                                             0, (long long)SS * EE, (long long)EE * SS, 1.0f);
    }

    // 3. scores = (q @ k^T) * scale  (1-pass fp16)
    {
        dim3 grid(SS / 128, SS / 128, BB);
        tc_gemm<0><<<grid, 256, GEMM_SMEM>>>(q_h, k_h, sc, nullptr,
                                             SS, SS, EE,
                                             (long long)SS * EE, (long long)SS * EE,
                                             (long long)SS * SS, scale);
    }

    // 4. softmax -> fp16 attn
    softmax_split_kernel<<<BB * SS, 256>>>(sc, at_h);

    // 5. out = attn @ v
    {
        dim3 grid(EE / 128, SS / 128, BB);
        tc_gemm<0><<<grid, 256, GEMM_SMEM>>>(at_h, vt_h, out, nullptr,
                                             SS, EE, SS,
                                             (long long)SS * SS, (long long)EE * SS,
                                             (long long)SS * EE, 1.0f);
    }
}